// round 13
// baseline (speedup 1.0000x reference)
#include <cuda_runtime.h>
#include <cuda_fp16.h>
#include <math.h>
#include <float.h>

#define Nn 100000
#define Ff 256
#define Hh 64
#define Ee 800000
#define Rr 7
#define TILE 64
#define BS 68

typedef unsigned long long ull;
typedef unsigned int uint;

__device__ __half d_h[Nn * Hh];
__device__ __half d_A[Nn * Hh];
__device__ __half d_B[Nn * Hh];
__device__ __half d_S[Nn * Hh];
__device__ float d_cnt[Nn];
__device__ float d_C[Rr * Hh];
__device__ float d_colsum[Hh];
__device__ int   d_colmax[Hh];

__device__ __forceinline__ ull pk2(float a, float b) {
    ull r; asm("mov.b64 %0, {%1,%2};" : "=l"(r) : "f"(a), "f"(b)); return r;
}
__device__ __forceinline__ float2 upk2(ull v) {
    float2 f; asm("mov.b64 {%0,%1}, %2;" : "=f"(f.x), "=f"(f.y) : "l"(v)); return f;
}
__device__ __forceinline__ void fma2(ull &d, ull a, ull b) {
    asm("fma.rn.f32x2 %0, %1, %2, %0;" : "+l"(d) : "l"(a), "l"(b));
}
__device__ __forceinline__ void atomicMaxFloat(int* addr, float v) {
    if (v >= 0.f) atomicMax(addr, __float_as_int(v));
    else          atomicMin((unsigned int*)addr, __float_as_uint(v));
}

// colsum/colmax init folded in here
__global__ void k_relC(const float* __restrict__ rel_emb, const float* __restrict__ Wm1) {
    int t = threadIdx.x;
    if (t < Hh) { d_colsum[t] = 0.f; d_colmax[t] = __float_as_int(-FLT_MAX); }
    if (t >= Rr * Hh) return;
    int r = t / Hh, j = t % Hh;
    float s = 0.f;
    for (int k = 0; k < Hh; k++) s += rel_emb[r * Hh + k] * Wm1[(128 + k) * Hh + j];
    d_C[t] = s;
}

__global__ __launch_bounds__(256) void k_node(
    const float* __restrict__ X,
    const float* __restrict__ W1, const float* __restrict__ b1,
    const float* __restrict__ g1, const float* __restrict__ be1,
    const float* __restrict__ W2, const float* __restrict__ b2,
    const float* __restrict__ Wm1)
{
    __shared__ __align__(16) float buf[64 * BS];
    __shared__ __align__(16) float sW[64 * 64];
    __shared__ float sb1[64], sg1[64], sbe1[64], sb2[64];

    int tid = threadIdx.x;
    int n0 = blockIdx.x * TILE;
    int nvalid = min(TILE, Nn - n0);
    if (tid < 64) { sb1[tid] = b1[tid]; sg1[tid] = g1[tid]; sbe1[tid] = be1[tid]; sb2[tid] = b2[tid]; }

    int tx = tid & 31, ty = tid >> 5;
    int c0 = 2 * tx, r0 = 8 * ty;

    ull acc[4][2];
#pragma unroll
    for (int p = 0; p < 4; p++) { acc[p][0] = 0ull; acc[p][1] = 0ull; }

    // GEMM1: Y = X @ W1  (K=256 in 4 chunks of 64)
    for (int kc = 0; kc < 4; kc++) {
        for (int i = 0; i < 4; i++) {
            int f = tid + i * 256;
            int r = f & 63;
            int k4 = (f >> 6) * 4;
            float4 v = make_float4(0.f, 0.f, 0.f, 0.f);
            if (r < nvalid) v = *(const float4*)(X + (size_t)(n0 + r) * Ff + kc * 64 + k4);
            buf[(k4 + 0) * BS + r] = v.x;
            buf[(k4 + 1) * BS + r] = v.y;
            buf[(k4 + 2) * BS + r] = v.z;
            buf[(k4 + 3) * BS + r] = v.w;
        }
        for (int i = 0; i < 4; i++) {
            int f = tid + i * 256;
            *(float4*)(sW + f * 4) = *(const float4*)(W1 + kc * 64 * 64 + f * 4);
        }
        __syncthreads();
#pragma unroll 4
        for (int k = 0; k < 64; k++) {
            ulonglong2 xa = *(const ulonglong2*)(buf + k * BS + r0);
            ulonglong2 xb = *(const ulonglong2*)(buf + k * BS + r0 + 4);
            float2 w = *(const float2*)(sW + k * 64 + c0);
            ull wd0 = pk2(w.x, w.x), wd1 = pk2(w.y, w.y);
            fma2(acc[0][0], xa.x, wd0); fma2(acc[0][1], xa.x, wd1);
            fma2(acc[1][0], xa.y, wd0); fma2(acc[1][1], xa.y, wd1);
            fma2(acc[2][0], xb.x, wd0); fma2(acc[2][1], xb.x, wd1);
            fma2(acc[3][0], xb.y, wd0); fma2(acc[3][1], xb.y, wd1);
        }
        __syncthreads();
    }

#pragma unroll
    for (int p = 0; p < 4; p++)
#pragma unroll
        for (int c = 0; c < 2; c++) {
            float2 v = upk2(acc[p][c]);
            float bb = sb1[c0 + c];
            *(float2*)(buf + (c0 + c) * BS + r0 + 2 * p) = make_float2(v.x + bb, v.y + bb);
        }
    for (int i = 0; i < 4; i++) {
        int f = tid + i * 256;
        *(float4*)(sW + f * 4) = *(const float4*)(W2 + f * 4);
    }
    __syncthreads();

    if (tid < 64) {
        int r = tid;
        float s = 0.f, s2 = 0.f;
        for (int c = 0; c < 64; c++) { float x = buf[c * BS + r]; s += x; s2 += x * x; }
        float mu = s * (1.f / 64.f);
        float var = s2 * (1.f / 64.f) - mu * mu;
        float rs = rsqrtf(var + 1e-5f);
        for (int c = 0; c < 64; c++) {
            float x = buf[c * BS + r];
            float v = (x - mu) * rs * sg1[c] + sbe1[c];
            buf[c * BS + r] = fmaxf(v, 0.f);
        }
    }
    __syncthreads();

    // GEMM2: h = relu(h1n @ W2 + b2)
    ull a2[4][2];
#pragma unroll
    for (int p = 0; p < 4; p++) { a2[p][0] = 0ull; a2[p][1] = 0ull; }
#pragma unroll 4
    for (int k = 0; k < 64; k++) {
        ulonglong2 xa = *(const ulonglong2*)(buf + k * BS + r0);
        ulonglong2 xb = *(const ulonglong2*)(buf + k * BS + r0 + 4);
        float2 w = *(const float2*)(sW + k * 64 + c0);
        ull wd0 = pk2(w.x, w.x), wd1 = pk2(w.y, w.y);
        fma2(a2[0][0], xa.x, wd0); fma2(a2[0][1], xa.x, wd1);
        fma2(a2[1][0], xa.y, wd0); fma2(a2[1][1], xa.y, wd1);
        fma2(a2[2][0], xb.x, wd0); fma2(a2[2][1], xb.x, wd1);
        fma2(a2[3][0], xb.y, wd0); fma2(a2[3][1], xb.y, wd1);
    }
    __syncthreads();

#pragma unroll
    for (int p = 0; p < 4; p++)
#pragma unroll
        for (int c = 0; c < 2; c++) {
            float2 v = upk2(a2[p][c]);
            float bb = sb2[c0 + c];
            *(float2*)(buf + (c0 + c) * BS + r0 + 2 * p) =
                make_float2(fmaxf(v.x + bb, 0.f), fmaxf(v.y + bb, 0.f));
        }
    for (int i = 0; i < 4; i++) {
        int f = tid + i * 256;
        *(float4*)(sW + f * 4) = *(const float4*)(Wm1 + f * 4);
    }
    __syncthreads();

    // store h (coalesced, fp16: 8 cols = 16B per lane-pair step)
    for (int i = 0; i < 2; i++) {
        int f = tid + i * 256;          // 0..511
        int r = f >> 3, c8 = (f & 7) * 8;
        if (r < nvalid) {
            __half2 h0 = __floats2half2_rn(buf[(c8 + 0) * BS + r], buf[(c8 + 1) * BS + r]);
            __half2 h1 = __floats2half2_rn(buf[(c8 + 2) * BS + r], buf[(c8 + 3) * BS + r]);
            __half2 h2 = __floats2half2_rn(buf[(c8 + 4) * BS + r], buf[(c8 + 5) * BS + r]);
            __half2 h3 = __floats2half2_rn(buf[(c8 + 6) * BS + r], buf[(c8 + 7) * BS + r]);
            uint4 pk = make_uint4(*(uint*)&h0, *(uint*)&h1, *(uint*)&h2, *(uint*)&h3);
            *(uint4*)(d_h + (size_t)(n0 + r) * 64 + c8) = pk;
        }
    }

    // GEMM3: A = h @ Wm1[0:64]  (col-pair layout), fp16 output
    int tx2 = tid & 15, ty2 = tid >> 4;
    int cc0 = 4 * tx2, rr0 = 4 * ty2;
    ull a3[4][2];
#pragma unroll
    for (int p = 0; p < 4; p++) { a3[p][0] = 0ull; a3[p][1] = 0ull; }
#pragma unroll 4
    for (int k = 0; k < 64; k++) {
        float x0 = buf[k * BS + rr0 + 0];
        float x1 = buf[k * BS + rr0 + 1];
        float x2 = buf[k * BS + rr0 + 2];
        float x3 = buf[k * BS + rr0 + 3];
        ulonglong2 wp = *(const ulonglong2*)(sW + k * 64 + cc0);
        ull xd0 = pk2(x0, x0), xd1 = pk2(x1, x1), xd2 = pk2(x2, x2), xd3 = pk2(x3, x3);
        fma2(a3[0][0], xd0, wp.x); fma2(a3[0][1], xd0, wp.y);
        fma2(a3[1][0], xd1, wp.x); fma2(a3[1][1], xd1, wp.y);
        fma2(a3[2][0], xd2, wp.x); fma2(a3[2][1], xd2, wp.y);
        fma2(a3[3][0], xd3, wp.x); fma2(a3[3][1], xd3, wp.y);
    }
    __syncthreads();
    for (int i = 0; i < 4; i++) {
        int f = tid + i * 256;
        *(float4*)(sW + f * 4) = *(const float4*)(Wm1 + 64 * 64 + f * 4);
    }
#pragma unroll
    for (int p = 0; p < 4; p++) {
        int rr = rr0 + p;
        if (rr < nvalid) {
#pragma unroll
            for (int q = 0; q < 2; q++) {
                float2 v = upk2(a3[p][q]);
                *(__half2*)(d_A + (size_t)(n0 + rr) * 64 + cc0 + 2 * q) = __float22half2_rn(v);
            }
        }
    }
    __syncthreads();

    // GEMM4: B = h @ Wm1[64:128], fp16 output
    ull a4[4][2];
#pragma unroll
    for (int p = 0; p < 4; p++) { a4[p][0] = 0ull; a4[p][1] = 0ull; }
#pragma unroll 4
    for (int k = 0; k < 64; k++) {
        float x0 = buf[k * BS + rr0 + 0];
        float x1 = buf[k * BS + rr0 + 1];
        float x2 = buf[k * BS + rr0 + 2];
        float x3 = buf[k * BS + rr0 + 3];
        ulonglong2 wp = *(const ulonglong2*)(sW + k * 64 + cc0);
        ull xd0 = pk2(x0, x0), xd1 = pk2(x1, x1), xd2 = pk2(x2, x2), xd3 = pk2(x3, x3);
        fma2(a4[0][0], xd0, wp.x); fma2(a4[0][1], xd0, wp.y);
        fma2(a4[1][0], xd1, wp.x); fma2(a4[1][1], xd1, wp.y);
        fma2(a4[2][0], xd2, wp.x); fma2(a4[2][1], xd2, wp.y);
        fma2(a4[3][0], xd3, wp.x); fma2(a4[3][1], xd3, wp.y);
    }
#pragma unroll
    for (int p = 0; p < 4; p++) {
        int rr = rr0 + p;
        if (rr < nvalid) {
#pragma unroll
            for (int q = 0; q < 2; q++) {
                float2 v = upk2(a4[p][q]);
                *(__half2*)(d_B + (size_t)(n0 + rr) * 64 + cc0 + 2 * q) = __float22half2_rn(v);
            }
        }
    }

    // fused init: zero this tile's d_S rows (fp16: 128B/row) and d_cnt
#pragma unroll
    for (int i = 0; i < 2; i++) {
        int idx = tid + i * 256;          // 0..511
        int r = idx >> 3, q = idx & 7;
        if (r < nvalid)
            ((uint4*)(d_S + (size_t)(n0 + r) * 64))[q] = make_uint4(0u, 0u, 0u, 0u);
    }
    if (tid < TILE && tid < nvalid) d_cnt[n0 + tid] = 0.f;
}

// Edge pass: 2 edges per 16-lane group, fp16 A/B gathers + fp16 vector atomics
__global__ __launch_bounds__(256) void k_edge(
    const float* __restrict__ edges,
    const float* __restrict__ Wm1, const float* __restrict__ bm1)
{
    __shared__ float sC[Rr * 64];
    __shared__ float swl[64], sbm1[64];
    int tid = threadIdx.x;
    for (int i = tid; i < Rr * 64; i += 256) sC[i] = d_C[i];
    if (tid < 64) { swl[tid] = Wm1[192 * 64 + tid]; sbm1[tid] = bm1[tid]; }
    __syncthreads();

    const int half = Ee / 2;
    int g = (blockIdx.x * 256 + tid) >> 4;
    int sub = tid & 15;
    if (g >= half) return;
    int c4 = sub * 4;

    float4 e0 = *(const float4*)(edges + (size_t)g * 4);
    float4 e1 = *(const float4*)(edges + (size_t)(g + half) * 4);
    int s0 = (int)e0.x, d0 = (int)e0.y, r0 = (int)e0.z; float w0 = e0.w;
    int s1 = (int)e1.x, d1 = (int)e1.y, r1 = (int)e1.z; float w1 = e1.w;

    uint2 au0 = *(const uint2*)(d_A + (size_t)s0 * 64 + c4);
    uint2 bu0 = *(const uint2*)(d_B + (size_t)d0 * 64 + c4);
    uint2 au1 = *(const uint2*)(d_A + (size_t)s1 * 64 + c4);
    uint2 bu1 = *(const uint2*)(d_B + (size_t)d1 * 64 + c4);

    float2 a0lo = __half22float2(*(__half2*)&au0.x), a0hi = __half22float2(*(__half2*)&au0.y);
    float2 b0lo = __half22float2(*(__half2*)&bu0.x), b0hi = __half22float2(*(__half2*)&bu0.y);
    float2 a1lo = __half22float2(*(__half2*)&au1.x), a1hi = __half22float2(*(__half2*)&au1.y);
    float2 b1lo = __half22float2(*(__half2*)&bu1.x), b1hi = __half22float2(*(__half2*)&bu1.y);

    float4 c0v = *(const float4*)(sC + r0 * 64 + c4);
    float4 c1v = *(const float4*)(sC + r1 * 64 + c4);
    float4 wl = *(const float4*)(swl + c4);
    float4 bm = *(const float4*)(sbm1 + c4);

    float4 v0, v1;
    v0.x = fmaxf(a0lo.x + b0lo.x + c0v.x + w0 * wl.x + bm.x, 0.f);
    v0.y = fmaxf(a0lo.y + b0lo.y + c0v.y + w0 * wl.y + bm.y, 0.f);
    v0.z = fmaxf(a0hi.x + b0hi.x + c0v.z + w0 * wl.z + bm.z, 0.f);
    v0.w = fmaxf(a0hi.y + b0hi.y + c0v.w + w0 * wl.w + bm.w, 0.f);
    v1.x = fmaxf(a1lo.x + b1lo.x + c1v.x + w1 * wl.x + bm.x, 0.f);
    v1.y = fmaxf(a1lo.y + b1lo.y + c1v.y + w1 * wl.y + bm.y, 0.f);
    v1.z = fmaxf(a1hi.x + b1hi.x + c1v.z + w1 * wl.z + bm.z, 0.f);
    v1.w = fmaxf(a1hi.y + b1hi.y + c1v.w + w1 * wl.w + bm.w, 0.f);

    __half2 p0lo = __floats2half2_rn(v0.x, v0.y), p0hi = __floats2half2_rn(v0.z, v0.w);
    __half2 p1lo = __floats2half2_rn(v1.x, v1.y), p1hi = __floats2half2_rn(v1.z, v1.w);

    __half* p0 = d_S + (size_t)d0 * 64 + c4;
    __half* p1 = d_S + (size_t)d1 * 64 + c4;
    asm volatile("red.global.add.noftz.v2.f16x2 [%0], {%1,%2};"
                 :: "l"(p0), "r"(*(uint*)&p0lo), "r"(*(uint*)&p0hi) : "memory");
    asm volatile("red.global.add.noftz.v2.f16x2 [%0], {%1,%2};"
                 :: "l"(p1), "r"(*(uint*)&p1lo), "r"(*(uint*)&p1hi) : "memory");
    if (sub == 0) { atomicAdd(&d_cnt[d0], 1.f); atomicAdd(&d_cnt[d1], 1.f); }
}

__global__ __launch_bounds__(256) void k_agg(
    const float* __restrict__ Wm2, const float* __restrict__ bm2,
    const float* __restrict__ gn,  const float* __restrict__ bn)
{
    __shared__ __align__(16) float buf[64 * BS];
    __shared__ __align__(16) float sW[64 * 64];
    __shared__ float sbm2[64], sgn[64], sbn[64];
    __shared__ float red_s[4 * 64];
    __shared__ float red_m[4 * 64];

    int tid = threadIdx.x;
    int n0 = blockIdx.x * TILE;
    int nvalid = min(TILE, Nn - n0);
    if (tid < 64) { sbm2[tid] = bm2[tid]; sgn[tid] = gn[tid]; sbn[tid] = bn[tid]; }

    for (int i = 0; i < 4; i++) {
        int f = tid + i * 256;
        int r = f & 63;
        int k4 = (f >> 6) * 4;
        float4 v = make_float4(0.f, 0.f, 0.f, 0.f);
        if (r < nvalid) {
            uint2 hv = *(const uint2*)(d_S + (size_t)(n0 + r) * 64 + k4);
            float2 lo = __half22float2(*(__half2*)&hv.x);
            float2 hi = __half22float2(*(__half2*)&hv.y);
            v = make_float4(lo.x, lo.y, hi.x, hi.y);
        }
        buf[(k4 + 0) * BS + r] = v.x;
        buf[(k4 + 1) * BS + r] = v.y;
        buf[(k4 + 2) * BS + r] = v.z;
        buf[(k4 + 3) * BS + r] = v.w;
    }
    for (int i = 0; i < 4; i++) {
        int f = tid + i * 256;
        *(float4*)(sW + f * 4) = *(const float4*)(Wm2 + f * 4);
    }
    __syncthreads();

    int tx = tid & 31, ty = tid >> 5;
    int c0 = 2 * tx, r0 = 8 * ty;
    ull acc[4][2];
#pragma unroll
    for (int p = 0; p < 4; p++) { acc[p][0] = 0ull; acc[p][1] = 0ull; }
#pragma unroll 4
    for (int k = 0; k < 64; k++) {
        ulonglong2 xa = *(const ulonglong2*)(buf + k * BS + r0);
        ulonglong2 xb = *(const ulonglong2*)(buf + k * BS + r0 + 4);
        float2 w = *(const float2*)(sW + k * 64 + c0);
        ull wd0 = pk2(w.x, w.x), wd1 = pk2(w.y, w.y);
        fma2(acc[0][0], xa.x, wd0); fma2(acc[0][1], xa.x, wd1);
        fma2(acc[1][0], xa.y, wd0); fma2(acc[1][1], xa.y, wd1);
        fma2(acc[2][0], xb.x, wd0); fma2(acc[2][1], xb.x, wd1);
        fma2(acc[3][0], xb.y, wd0); fma2(acc[3][1], xb.y, wd1);
    }
    __syncthreads();

#pragma unroll
    for (int p = 0; p < 4; p++) {
        int rr = r0 + 2 * p;
        float cnt0 = (rr     < nvalid) ? d_cnt[n0 + rr]     : 0.f;
        float cnt1 = (rr + 1 < nvalid) ? d_cnt[n0 + rr + 1] : 0.f;
        float2 h0 = make_float2(0.f, 0.f), h1 = make_float2(0.f, 0.f);
        if (rr < nvalid) {
            __half2 hh = *(const __half2*)(d_h + (size_t)(n0 + rr) * 64 + c0);
            h0 = __half22float2(hh);
        }
        if (rr + 1 < nvalid) {
            __half2 hh = *(const __half2*)(d_h + (size_t)(n0 + rr + 1) * 64 + c0);
            h1 = __half22float2(hh);
        }
        float2 v0 = upk2(acc[p][0]);
        float2 v1 = upk2(acc[p][1]);
        buf[(c0    ) * BS + rr    ] = v0.x + cnt0 * sbm2[c0    ] + h0.x;
        buf[(c0    ) * BS + rr + 1] = v0.y + cnt1 * sbm2[c0    ] + h1.x;
        buf[(c0 + 1) * BS + rr    ] = v1.x + cnt0 * sbm2[c0 + 1] + h0.y;
        buf[(c0 + 1) * BS + rr + 1] = v1.y + cnt1 * sbm2[c0 + 1] + h1.y;
    }
    __syncthreads();

    if (tid < 64 && tid < nvalid) {
        int r = tid;
        float s = 0.f, s2 = 0.f;
        for (int c = 0; c < 64; c++) { float x = buf[c * BS + r]; s += x; s2 += x * x; }
        float mu = s * (1.f / 64.f);
        float var = s2 * (1.f / 64.f) - mu * mu;
        float rs = rsqrtf(var + 1e-5f);
        for (int c = 0; c < 64; c++) {
            float x = buf[c * BS + r];
            buf[c * BS + r] = (x - mu) * rs * sgn[c] + sbn[c];
        }
    }
    __syncthreads();

    {
        int c = tid & 63, q = tid >> 6;
        float s = 0.f, m = -FLT_MAX;
        int rbeg = q * 16;
        int rend = min(rbeg + 16, nvalid);
        for (int r = rbeg; r < rend; r++) {
            float v = buf[c * BS + r];
            s += v;
            m = fmaxf(m, v);
        }
        red_s[q * 64 + c] = s;
        red_m[q * 64 + c] = m;
    }
    __syncthreads();
    if (tid < 64) {
        float s = red_s[tid] + red_s[64 + tid] + red_s[128 + tid] + red_s[192 + tid];
        float m = fmaxf(fmaxf(red_m[tid], red_m[64 + tid]),
                        fmaxf(red_m[128 + tid], red_m[192 + tid]));
        atomicAdd(&d_colsum[tid], s);
        atomicMaxFloat(&d_colmax[tid], m);
    }
}

__global__ void k_final(const float* __restrict__ Wg1, const float* __restrict__ bg1,
                        const float* __restrict__ Wg2, const float* __restrict__ bg2,
                        float* __restrict__ out)
{
    __shared__ float sg[128], st[64];
    int t = threadIdx.x;
    if (t < 64)       sg[t] = d_colsum[t] * (1.0f / (float)Nn);
    else if (t < 128) sg[t] = __int_as_float(d_colmax[t - 64]);
    __syncthreads();
    if (t < 64) {
        float s = bg1[t];
        for (int k = 0; k < 128; k++) s += sg[k] * Wg1[k * 64 + t];
        st[t] = fmaxf(s, 0.f);
    }
    __syncthreads();
    if (t < 64) {
        float s = bg2[t];
        for (int k = 0; k < 64; k++) s += st[k] * Wg2[k * 64 + t];
        out[t] = s;
    }
}

extern "C" void kernel_launch(void* const* d_in, const int* in_sizes, int n_in,
                              void* d_out, int out_size)
{
    const float* X      = (const float*)d_in[0];
    const float* edges  = (const float*)d_in[1];
    const float* W1     = (const float*)d_in[2];
    const float* b1     = (const float*)d_in[3];
    const float* g1     = (const float*)d_in[4];
    const float* be1    = (const float*)d_in[5];
    const float* W2     = (const float*)d_in[6];
    const float* b2     = (const float*)d_in[7];
    const float* rel_emb= (const float*)d_in[8];
    const float* Wm1    = (const float*)d_in[9];
    const float* bm1    = (const float*)d_in[10];
    const float* Wm2    = (const float*)d_in[11];
    const float* bm2    = (const float*)d_in[12];
    const float* gn     = (const float*)d_in[13];
    const float* bn     = (const float*)d_in[14];
    const float* Wg1    = (const float*)d_in[15];
    const float* bg1    = (const float*)d_in[16];
    const float* Wg2    = (const float*)d_in[17];
    const float* bg2    = (const float*)d_in[18];
    float* out = (float*)d_out;

    k_relC<<<1, 512>>>(rel_emb, Wm1);
    int nblocks = (Nn + TILE - 1) / TILE;
    k_node<<<nblocks, 256>>>(X, W1, b1, g1, be1, W2, b2, Wm1);
    int eblocks = ((Ee / 2) * 16 + 255) / 256;
    k_edge<<<eblocks, 256>>>(edges, Wm1, bm1);
    k_agg<<<nblocks, 256>>>(Wm2, bm2, gn, bn);
    k_final<<<1, 128>>>(Wg1, bg1, Wg2, bg2, out);
}

// round 14
// speedup vs baseline: 1.0017x; 1.0017x over previous
#include <cuda_runtime.h>
#include <cuda_fp16.h>
#include <math.h>
#include <float.h>

#define Nn 100000
#define Ff 256
#define Hh 64
#define Ee 800000
#define Rr 7
#define TILE 64
#define BS 68

typedef unsigned long long ull;
typedef unsigned int uint;

__device__ float d_h[Nn * Hh];
__device__ __half d_A[Nn * Hh];
__device__ __half d_B[Nn * Hh];
__device__ __half d_S[Nn * Hh];
__device__ float d_cnt[Nn];
__device__ float d_C[Rr * Hh];
__device__ float d_colsum[Hh];
__device__ int   d_colmax[Hh];

__device__ __forceinline__ ull pk2(float a, float b) {
    ull r; asm("mov.b64 %0, {%1,%2};" : "=l"(r) : "f"(a), "f"(b)); return r;
}
__device__ __forceinline__ float2 upk2(ull v) {
    float2 f; asm("mov.b64 {%0,%1}, %2;" : "=f"(f.x), "=f"(f.y) : "l"(v)); return f;
}
__device__ __forceinline__ void fma2(ull &d, ull a, ull b) {
    asm("fma.rn.f32x2 %0, %1, %2, %0;" : "+l"(d) : "l"(a), "l"(b));
}
__device__ __forceinline__ void atomicMaxFloat(int* addr, float v) {
    if (v >= 0.f) atomicMax(addr, __float_as_int(v));
    else          atomicMin((unsigned int*)addr, __float_as_uint(v));
}

// colsum/colmax init folded in here
__global__ void k_relC(const float* __restrict__ rel_emb, const float* __restrict__ Wm1) {
    int t = threadIdx.x;
    if (t < Hh) { d_colsum[t] = 0.f; d_colmax[t] = __float_as_int(-FLT_MAX); }
    if (t >= Rr * Hh) return;
    int r = t / Hh, j = t % Hh;
    float s = 0.f;
    for (int k = 0; k < Hh; k++) s += rel_emb[r * Hh + k] * Wm1[(128 + k) * Hh + j];
    d_C[t] = s;
}

__global__ __launch_bounds__(256) void k_node(
    const float* __restrict__ X,
    const float* __restrict__ W1, const float* __restrict__ b1,
    const float* __restrict__ g1, const float* __restrict__ be1,
    const float* __restrict__ W2, const float* __restrict__ b2,
    const float* __restrict__ Wm1)
{
    __shared__ __align__(16) float buf[64 * BS];
    __shared__ __align__(16) float sW[64 * 64];
    __shared__ float sb1[64], sg1[64], sbe1[64], sb2[64];

    int tid = threadIdx.x;
    int n0 = blockIdx.x * TILE;
    int nvalid = min(TILE, Nn - n0);
    if (tid < 64) { sb1[tid] = b1[tid]; sg1[tid] = g1[tid]; sbe1[tid] = be1[tid]; sb2[tid] = b2[tid]; }

    int tx = tid & 31, ty = tid >> 5;
    int c0 = 2 * tx, r0 = 8 * ty;

    ull acc[4][2];
#pragma unroll
    for (int p = 0; p < 4; p++) { acc[p][0] = 0ull; acc[p][1] = 0ull; }

    // GEMM1: Y = X @ W1  (K=256 in 4 chunks of 64)
    // X staged with coalesced LDG (row-major) + XOR-swizzled transpose STS.
    for (int kc = 0; kc < 4; kc++) {
        {
            int r = tid >> 4;             // 0..15 (+16 per i)
            int cq = tid & 15;            // k-quarter 0..15
            int xk = (cq & 7) << 2;       // swizzle bits 2-4
#pragma unroll
            for (int i = 0; i < 4; i++) {
                int rr = r + i * 16;
                float4 v = make_float4(0.f, 0.f, 0.f, 0.f);
                if (rr < nvalid)
                    v = *(const float4*)(X + (size_t)(n0 + rr) * Ff + kc * 64 + cq * 4);
                int rs = rr ^ xk;
                buf[(cq * 4 + 0) * BS + rs] = v.x;
                buf[(cq * 4 + 1) * BS + rs] = v.y;
                buf[(cq * 4 + 2) * BS + rs] = v.z;
                buf[(cq * 4 + 3) * BS + rs] = v.w;
            }
        }
        for (int i = 0; i < 4; i++) {
            int f = tid + i * 256;
            *(float4*)(sW + f * 4) = *(const float4*)(W1 + kc * 64 * 64 + f * 4);
        }
        __syncthreads();
#pragma unroll 4
        for (int k = 0; k < 64; k++) {
            int xk = ((k >> 2) & 7) << 2;
            ulonglong2 xa = *(const ulonglong2*)(buf + k * BS + (r0 ^ xk));
            ulonglong2 xb = *(const ulonglong2*)(buf + k * BS + ((r0 + 4) ^ xk));
            float2 w = *(const float2*)(sW + k * 64 + c0);
            ull wd0 = pk2(w.x, w.x), wd1 = pk2(w.y, w.y);
            fma2(acc[0][0], xa.x, wd0); fma2(acc[0][1], xa.x, wd1);
            fma2(acc[1][0], xa.y, wd0); fma2(acc[1][1], xa.y, wd1);
            fma2(acc[2][0], xb.x, wd0); fma2(acc[2][1], xb.x, wd1);
            fma2(acc[3][0], xb.y, wd0); fma2(acc[3][1], xb.y, wd1);
        }
        __syncthreads();
    }

#pragma unroll
    for (int p = 0; p < 4; p++)
#pragma unroll
        for (int c = 0; c < 2; c++) {
            float2 v = upk2(acc[p][c]);
            float bb = sb1[c0 + c];
            *(float2*)(buf + (c0 + c) * BS + r0 + 2 * p) = make_float2(v.x + bb, v.y + bb);
        }
    for (int i = 0; i < 4; i++) {
        int f = tid + i * 256;
        *(float4*)(sW + f * 4) = *(const float4*)(W2 + f * 4);
    }
    __syncthreads();

    if (tid < 64) {
        int r = tid;
        float s = 0.f, s2 = 0.f;
        for (int c = 0; c < 64; c++) { float x = buf[c * BS + r]; s += x; s2 += x * x; }
        float mu = s * (1.f / 64.f);
        float var = s2 * (1.f / 64.f) - mu * mu;
        float rs = rsqrtf(var + 1e-5f);
        for (int c = 0; c < 64; c++) {
            float x = buf[c * BS + r];
            float v = (x - mu) * rs * sg1[c] + sbe1[c];
            buf[c * BS + r] = fmaxf(v, 0.f);
        }
    }
    __syncthreads();

    // GEMM2: h = relu(h1n @ W2 + b2)
    ull a2[4][2];
#pragma unroll
    for (int p = 0; p < 4; p++) { a2[p][0] = 0ull; a2[p][1] = 0ull; }
#pragma unroll 4
    for (int k = 0; k < 64; k++) {
        ulonglong2 xa = *(const ulonglong2*)(buf + k * BS + r0);
        ulonglong2 xb = *(const ulonglong2*)(buf + k * BS + r0 + 4);
        float2 w = *(const float2*)(sW + k * 64 + c0);
        ull wd0 = pk2(w.x, w.x), wd1 = pk2(w.y, w.y);
        fma2(a2[0][0], xa.x, wd0); fma2(a2[0][1], xa.x, wd1);
        fma2(a2[1][0], xa.y, wd0); fma2(a2[1][1], xa.y, wd1);
        fma2(a2[2][0], xb.x, wd0); fma2(a2[2][1], xb.x, wd1);
        fma2(a2[3][0], xb.y, wd0); fma2(a2[3][1], xb.y, wd1);
    }
    __syncthreads();

#pragma unroll
    for (int p = 0; p < 4; p++)
#pragma unroll
        for (int c = 0; c < 2; c++) {
            float2 v = upk2(a2[p][c]);
            float bb = sb2[c0 + c];
            *(float2*)(buf + (c0 + c) * BS + r0 + 2 * p) =
                make_float2(fmaxf(v.x + bb, 0.f), fmaxf(v.y + bb, 0.f));
        }
    for (int i = 0; i < 4; i++) {
        int f = tid + i * 256;
        *(float4*)(sW + f * 4) = *(const float4*)(Wm1 + f * 4);
    }
    __syncthreads();

    // store h (coalesced, fp32)
    for (int i = 0; i < 4; i++) {
        int f = tid + i * 256;
        int r = f >> 4, c4 = (f & 15) * 4;
        if (r < nvalid) {
            float4 v;
            v.x = buf[(c4 + 0) * BS + r]; v.y = buf[(c4 + 1) * BS + r];
            v.z = buf[(c4 + 2) * BS + r]; v.w = buf[(c4 + 3) * BS + r];
            *(float4*)(d_h + (size_t)(n0 + r) * 64 + c4) = v;
        }
    }

    // GEMM3: A = h @ Wm1[0:64]  (col-pair layout), fp16 output
    int tx2 = tid & 15, ty2 = tid >> 4;
    int cc0 = 4 * tx2, rr0 = 4 * ty2;
    ull a3[4][2];
#pragma unroll
    for (int p = 0; p < 4; p++) { a3[p][0] = 0ull; a3[p][1] = 0ull; }
#pragma unroll 4
    for (int k = 0; k < 64; k++) {
        float x0 = buf[k * BS + rr0 + 0];
        float x1 = buf[k * BS + rr0 + 1];
        float x2 = buf[k * BS + rr0 + 2];
        float x3 = buf[k * BS + rr0 + 3];
        ulonglong2 wp = *(const ulonglong2*)(sW + k * 64 + cc0);
        ull xd0 = pk2(x0, x0), xd1 = pk2(x1, x1), xd2 = pk2(x2, x2), xd3 = pk2(x3, x3);
        fma2(a3[0][0], xd0, wp.x); fma2(a3[0][1], xd0, wp.y);
        fma2(a3[1][0], xd1, wp.x); fma2(a3[1][1], xd1, wp.y);
        fma2(a3[2][0], xd2, wp.x); fma2(a3[2][1], xd2, wp.y);
        fma2(a3[3][0], xd3, wp.x); fma2(a3[3][1], xd3, wp.y);
    }
    __syncthreads();
    for (int i = 0; i < 4; i++) {
        int f = tid + i * 256;
        *(float4*)(sW + f * 4) = *(const float4*)(Wm1 + 64 * 64 + f * 4);
    }
#pragma unroll
    for (int p = 0; p < 4; p++) {
        int rr = rr0 + p;
        if (rr < nvalid) {
#pragma unroll
            for (int q = 0; q < 2; q++) {
                float2 v = upk2(a3[p][q]);
                *(__half2*)(d_A + (size_t)(n0 + rr) * 64 + cc0 + 2 * q) = __float22half2_rn(v);
            }
        }
    }
    __syncthreads();

    // GEMM4: B = h @ Wm1[64:128], fp16 output
    ull a4[4][2];
#pragma unroll
    for (int p = 0; p < 4; p++) { a4[p][0] = 0ull; a4[p][1] = 0ull; }
#pragma unroll 4
    for (int k = 0; k < 64; k++) {
        float x0 = buf[k * BS + rr0 + 0];
        float x1 = buf[k * BS + rr0 + 1];
        float x2 = buf[k * BS + rr0 + 2];
        float x3 = buf[k * BS + rr0 + 3];
        ulonglong2 wp = *(const ulonglong2*)(sW + k * 64 + cc0);
        ull xd0 = pk2(x0, x0), xd1 = pk2(x1, x1), xd2 = pk2(x2, x2), xd3 = pk2(x3, x3);
        fma2(a4[0][0], xd0, wp.x); fma2(a4[0][1], xd0, wp.y);
        fma2(a4[1][0], xd1, wp.x); fma2(a4[1][1], xd1, wp.y);
        fma2(a4[2][0], xd2, wp.x); fma2(a4[2][1], xd2, wp.y);
        fma2(a4[3][0], xd3, wp.x); fma2(a4[3][1], xd3, wp.y);
    }
#pragma unroll
    for (int p = 0; p < 4; p++) {
        int rr = rr0 + p;
        if (rr < nvalid) {
#pragma unroll
            for (int q = 0; q < 2; q++) {
                float2 v = upk2(a4[p][q]);
                *(__half2*)(d_B + (size_t)(n0 + rr) * 64 + cc0 + 2 * q) = __float22half2_rn(v);
            }
        }
    }

    // fused init: zero this tile's d_S rows (fp16: 128B/row) and d_cnt
#pragma unroll
    for (int i = 0; i < 2; i++) {
        int idx = tid + i * 256;          // 0..511
        int r = idx >> 3, q = idx & 7;
        if (r < nvalid)
            ((uint4*)(d_S + (size_t)(n0 + r) * 64))[q] = make_uint4(0u, 0u, 0u, 0u);
    }
    if (tid < TILE && tid < nvalid) d_cnt[n0 + tid] = 0.f;
}

// Edge pass: 2 edges per 16-lane group, fp16 A/B gathers + fp16 vector atomics
__global__ __launch_bounds__(256) void k_edge(
    const float* __restrict__ edges,
    const float* __restrict__ Wm1, const float* __restrict__ bm1)
{
    __shared__ float sC[Rr * 64];
    __shared__ float swl[64], sbm1[64];
    int tid = threadIdx.x;
    for (int i = tid; i < Rr * 64; i += 256) sC[i] = d_C[i];
    if (tid < 64) { swl[tid] = Wm1[192 * 64 + tid]; sbm1[tid] = bm1[tid]; }
    __syncthreads();

    const int half = Ee / 2;
    int g = (blockIdx.x * 256 + tid) >> 4;
    int sub = tid & 15;
    if (g >= half) return;
    int c4 = sub * 4;

    float4 e0 = *(const float4*)(edges + (size_t)g * 4);
    float4 e1 = *(const float4*)(edges + (size_t)(g + half) * 4);
    int s0 = (int)e0.x, d0 = (int)e0.y, r0 = (int)e0.z; float w0 = e0.w;
    int s1 = (int)e1.x, d1 = (int)e1.y, r1 = (int)e1.z; float w1 = e1.w;

    uint2 au0 = *(const uint2*)(d_A + (size_t)s0 * 64 + c4);
    uint2 bu0 = *(const uint2*)(d_B + (size_t)d0 * 64 + c4);
    uint2 au1 = *(const uint2*)(d_A + (size_t)s1 * 64 + c4);
    uint2 bu1 = *(const uint2*)(d_B + (size_t)d1 * 64 + c4);

    float2 a0lo = __half22float2(*(__half2*)&au0.x), a0hi = __half22float2(*(__half2*)&au0.y);
    float2 b0lo = __half22float2(*(__half2*)&bu0.x), b0hi = __half22float2(*(__half2*)&bu0.y);
    float2 a1lo = __half22float2(*(__half2*)&au1.x), a1hi = __half22float2(*(__half2*)&au1.y);
    float2 b1lo = __half22float2(*(__half2*)&bu1.x), b1hi = __half22float2(*(__half2*)&bu1.y);

    float4 c0v = *(const float4*)(sC + r0 * 64 + c4);
    float4 c1v = *(const float4*)(sC + r1 * 64 + c4);
    float4 wl = *(const float4*)(swl + c4);
    float4 bm = *(const float4*)(sbm1 + c4);

    float4 v0, v1;
    v0.x = fmaxf(a0lo.x + b0lo.x + c0v.x + w0 * wl.x + bm.x, 0.f);
    v0.y = fmaxf(a0lo.y + b0lo.y + c0v.y + w0 * wl.y + bm.y, 0.f);
    v0.z = fmaxf(a0hi.x + b0hi.x + c0v.z + w0 * wl.z + bm.z, 0.f);
    v0.w = fmaxf(a0hi.y + b0hi.y + c0v.w + w0 * wl.w + bm.w, 0.f);
    v1.x = fmaxf(a1lo.x + b1lo.x + c1v.x + w1 * wl.x + bm.x, 0.f);
    v1.y = fmaxf(a1lo.y + b1lo.y + c1v.y + w1 * wl.y + bm.y, 0.f);
    v1.z = fmaxf(a1hi.x + b1hi.x + c1v.z + w1 * wl.z + bm.z, 0.f);
    v1.w = fmaxf(a1hi.y + b1hi.y + c1v.w + w1 * wl.w + bm.w, 0.f);

    __half2 p0lo = __floats2half2_rn(v0.x, v0.y), p0hi = __floats2half2_rn(v0.z, v0.w);
    __half2 p1lo = __floats2half2_rn(v1.x, v1.y), p1hi = __floats2half2_rn(v1.z, v1.w);

    __half* p0 = d_S + (size_t)d0 * 64 + c4;
    __half* p1 = d_S + (size_t)d1 * 64 + c4;
    asm volatile("red.global.add.noftz.v2.f16x2 [%0], {%1,%2};"
                 :: "l"(p0), "r"(*(uint*)&p0lo), "r"(*(uint*)&p0hi) : "memory");
    asm volatile("red.global.add.noftz.v2.f16x2 [%0], {%1,%2};"
                 :: "l"(p1), "r"(*(uint*)&p1lo), "r"(*(uint*)&p1hi) : "memory");
    if (sub == 0) { atomicAdd(&d_cnt[d0], 1.f); atomicAdd(&d_cnt[d1], 1.f); }
}

__global__ __launch_bounds__(256) void k_agg(
    const float* __restrict__ Wm2, const float* __restrict__ bm2,
    const float* __restrict__ gn,  const float* __restrict__ bn)
{
    __shared__ __align__(16) float buf[64 * BS];
    __shared__ __align__(16) float sW[64 * 64];
    __shared__ float sbm2[64], sgn[64], sbn[64];
    __shared__ float red_s[4 * 64];
    __shared__ float red_m[4 * 64];

    int tid = threadIdx.x;
    int n0 = blockIdx.x * TILE;
    int nvalid = min(TILE, Nn - n0);
    if (tid < 64) { sbm2[tid] = bm2[tid]; sgn[tid] = gn[tid]; sbn[tid] = bn[tid]; }

    for (int i = 0; i < 4; i++) {
        int f = tid + i * 256;
        int r = f & 63;
        int k4 = (f >> 6) * 4;
        float4 v = make_float4(0.f, 0.f, 0.f, 0.f);
        if (r < nvalid) {
            uint2 hv = *(const uint2*)(d_S + (size_t)(n0 + r) * 64 + k4);
            float2 lo = __half22float2(*(__half2*)&hv.x);
            float2 hi = __half22float2(*(__half2*)&hv.y);
            v = make_float4(lo.x, lo.y, hi.x, hi.y);
        }
        buf[(k4 + 0) * BS + r] = v.x;
        buf[(k4 + 1) * BS + r] = v.y;
        buf[(k4 + 2) * BS + r] = v.z;
        buf[(k4 + 3) * BS + r] = v.w;
    }
    for (int i = 0; i < 4; i++) {
        int f = tid + i * 256;
        *(float4*)(sW + f * 4) = *(const float4*)(Wm2 + f * 4);
    }
    __syncthreads();

    int tx = tid & 31, ty = tid >> 5;
    int c0 = 2 * tx, r0 = 8 * ty;
    ull acc[4][2];
#pragma unroll
    for (int p = 0; p < 4; p++) { acc[p][0] = 0ull; acc[p][1] = 0ull; }
#pragma unroll 4
    for (int k = 0; k < 64; k++) {
        ulonglong2 xa = *(const ulonglong2*)(buf + k * BS + r0);
        ulonglong2 xb = *(const ulonglong2*)(buf + k * BS + r0 + 4);
        float2 w = *(const float2*)(sW + k * 64 + c0);
        ull wd0 = pk2(w.x, w.x), wd1 = pk2(w.y, w.y);
        fma2(acc[0][0], xa.x, wd0); fma2(acc[0][1], xa.x, wd1);
        fma2(acc[1][0], xa.y, wd0); fma2(acc[1][1], xa.y, wd1);
        fma2(acc[2][0], xb.x, wd0); fma2(acc[2][1], xb.x, wd1);
        fma2(acc[3][0], xb.y, wd0); fma2(acc[3][1], xb.y, wd1);
    }
    __syncthreads();

#pragma unroll
    for (int p = 0; p < 4; p++) {
        int rr = r0 + 2 * p;
        float cnt0 = (rr     < nvalid) ? d_cnt[n0 + rr]     : 0.f;
        float cnt1 = (rr + 1 < nvalid) ? d_cnt[n0 + rr + 1] : 0.f;
        float2 h0 = (rr     < nvalid) ? *(const float2*)(d_h + (size_t)(n0 + rr)     * 64 + c0) : make_float2(0.f, 0.f);
        float2 h1 = (rr + 1 < nvalid) ? *(const float2*)(d_h + (size_t)(n0 + rr + 1) * 64 + c0) : make_float2(0.f, 0.f);
        float2 v0 = upk2(acc[p][0]);
        float2 v1 = upk2(acc[p][1]);
        buf[(c0    ) * BS + rr    ] = v0.x + cnt0 * sbm2[c0    ] + h0.x;
        buf[(c0    ) * BS + rr + 1] = v0.y + cnt1 * sbm2[c0    ] + h1.x;
        buf[(c0 + 1) * BS + rr    ] = v1.x + cnt0 * sbm2[c0 + 1] + h0.y;
        buf[(c0 + 1) * BS + rr + 1] = v1.y + cnt1 * sbm2[c0 + 1] + h1.y;
    }
    __syncthreads();

    if (tid < 64 && tid < nvalid) {
        int r = tid;
        float s = 0.f, s2 = 0.f;
        for (int c = 0; c < 64; c++) { float x = buf[c * BS + r]; s += x; s2 += x * x; }
        float mu = s * (1.f / 64.f);
        float var = s2 * (1.f / 64.f) - mu * mu;
        float rs = rsqrtf(var + 1e-5f);
        for (int c = 0; c < 64; c++) {
            float x = buf[c * BS + r];
            buf[c * BS + r] = (x - mu) * rs * sgn[c] + sbn[c];
        }
    }
    __syncthreads();

    {
        int c = tid & 63, q = tid >> 6;
        float s = 0.f, m = -FLT_MAX;
        int rbeg = q * 16;
        int rend = min(rbeg + 16, nvalid);
        for (int r = rbeg; r < rend; r++) {
            float v = buf[c * BS + r];
            s += v;
            m = fmaxf(m, v);
        }
        red_s[q * 64 + c] = s;
        red_m[q * 64 + c] = m;
    }
    __syncthreads();
    if (tid < 64) {
        float s = red_s[tid] + red_s[64 + tid] + red_s[128 + tid] + red_s[192 + tid];
        float m = fmaxf(fmaxf(red_m[tid], red_m[64 + tid]),
                        fmaxf(red_m[128 + tid], red_m[192 + tid]));
        atomicAdd(&d_colsum[tid], s);
        atomicMaxFloat(&d_colmax[tid], m);
    }
}

__global__ void k_final(const float* __restrict__ Wg1, const float* __restrict__ bg1,
                        const float* __restrict__ Wg2, const float* __restrict__ bg2,
                        float* __restrict__ out)
{
    __shared__ float sg[128], st[64];
    int t = threadIdx.x;
    if (t < 64)       sg[t] = d_colsum[t] * (1.0f / (float)Nn);
    else if (t < 128) sg[t] = __int_as_float(d_colmax[t - 64]);
    __syncthreads();
    if (t < 64) {
        float s = bg1[t];
        for (int k = 0; k < 128; k++) s += sg[k] * Wg1[k * 64 + t];
        st[t] = fmaxf(s, 0.f);
    }
    __syncthreads();
    if (t < 64) {
        float s = bg2[t];
        for (int k = 0; k < 64; k++) s += st[k] * Wg2[k * 64 + t];
        out[t] = s;
    }
}

extern "C" void kernel_launch(void* const* d_in, const int* in_sizes, int n_in,
                              void* d_out, int out_size)
{
    const float* X      = (const float*)d_in[0];
    const float* edges  = (const float*)d_in[1];
    const float* W1     = (const float*)d_in[2];
    const float* b1     = (const float*)d_in[3];
    const float* g1     = (const float*)d_in[4];
    const float* be1    = (const float*)d_in[5];
    const float* W2     = (const float*)d_in[6];
    const float* b2     = (const float*)d_in[7];
    const float* rel_emb= (const float*)d_in[8];
    const float* Wm1    = (const float*)d_in[9];
    const float* bm1    = (const float*)d_in[10];
    const float* Wm2    = (const float*)d_in[11];
    const float* bm2    = (const float*)d_in[12];
    const float* gn     = (const float*)d_in[13];
    const float* bn     = (const float*)d_in[14];
    const float* Wg1    = (const float*)d_in[15];
    const float* bg1    = (const float*)d_in[16];
    const float* Wg2    = (const float*)d_in[17];
    const float* bg2    = (const float*)d_in[18];
    float* out = (float*)d_out;

    k_relC<<<1, 512>>>(rel_emb, Wm1);
    int nblocks = (Nn + TILE - 1) / TILE;
    k_node<<<nblocks, 256>>>(X, W1, b1, g1, be1, W2, b2, Wm1);
    int eblocks = ((Ee / 2) * 16 + 255) / 256;
    k_edge<<<eblocks, 256>>>(edges, Wm1, bm1);
    k_agg<<<nblocks, 256>>>(Wm2, bm2, gn, bn);
    k_final<<<1, 128>>>(Wg1, bg1, Wg2, bg2, out);
}

// round 15
// speedup vs baseline: 1.3741x; 1.3717x over previous
#include <cuda_runtime.h>
#include <cuda_bf16.h>
#include <cuda_fp16.h>
#include <math.h>
#include <float.h>

#define Nn 100000
#define Ff 256
#define Hh 64
#define Ee 800000
#define Rr 7
#define TILE 64
#define BS 68

typedef unsigned long long ull;
typedef unsigned int uint;
typedef unsigned short ushort;

__device__ float  d_h[Nn * Hh];
__device__ __half d_A[Nn * Hh];
__device__ __half d_B[Nn * Hh];
__device__ __half d_S[Nn * Hh];
__device__ float d_cnt[Nn];
__device__ float d_C[Rr * Hh];
__device__ float d_colsum[Hh];
__device__ int   d_colmax[Hh];

__device__ __forceinline__ ull pk2(float a, float b) {
    ull r; asm("mov.b64 %0, {%1,%2};" : "=l"(r) : "f"(a), "f"(b)); return r;
}
__device__ __forceinline__ float2 upk2(ull v) {
    float2 f; asm("mov.b64 {%0,%1}, %2;" : "=f"(f.x), "=f"(f.y) : "l"(v)); return f;
}
__device__ __forceinline__ void fma2(ull &d, ull a, ull b) {
    asm("fma.rn.f32x2 %0, %1, %2, %0;" : "+l"(d) : "l"(a), "l"(b));
}
__device__ __forceinline__ void atomicMaxFloat(int* addr, float v) {
    if (v >= 0.f) atomicMax(addr, __float_as_int(v));
    else          atomicMin((unsigned int*)addr, __float_as_uint(v));
}
__device__ __forceinline__ uint smem_u32(const void* p) {
    uint a; asm("{ .reg .u64 t; cvta.to.shared.u64 t, %1; cvt.u32.u64 %0, t; }" : "=r"(a) : "l"(p));
    return a;
}
__device__ __forceinline__ void ldsm4(uint* r, uint addr) {
    asm volatile("ldmatrix.sync.aligned.m8n8.x4.shared.b16 {%0,%1,%2,%3}, [%4];"
        : "=r"(r[0]), "=r"(r[1]), "=r"(r[2]), "=r"(r[3]) : "r"(addr));
}
__device__ __forceinline__ void ldsm4t(uint* r, uint addr) {
    asm volatile("ldmatrix.sync.aligned.m8n8.x4.trans.shared.b16 {%0,%1,%2,%3}, [%4];"
        : "=r"(r[0]), "=r"(r[1]), "=r"(r[2]), "=r"(r[3]) : "r"(addr));
}
__device__ __forceinline__ void mma_bf16(float* d, const uint* a, uint b0, uint b1) {
    asm volatile("mma.sync.aligned.m16n8k16.row.col.f32.bf16.bf16.f32 "
        "{%0,%1,%2,%3}, {%4,%5,%6,%7}, {%8,%9}, {%0,%1,%2,%3};"
        : "+f"(d[0]), "+f"(d[1]), "+f"(d[2]), "+f"(d[3])
        : "r"(a[0]), "r"(a[1]), "r"(a[2]), "r"(a[3]), "r"(b0), "r"(b1));
}

// colsum/colmax init folded in here
__global__ void k_relC(const float* __restrict__ rel_emb, const float* __restrict__ Wm1) {
    int t = threadIdx.x;
    if (t < Hh) { d_colsum[t] = 0.f; d_colmax[t] = __float_as_int(-FLT_MAX); }
    if (t >= Rr * Hh) return;
    int r = t / Hh, j = t % Hh;
    float s = 0.f;
    for (int k = 0; k < Hh; k++) s += rel_emb[r * Hh + k] * Wm1[(128 + k) * Hh + j];
    d_C[t] = s;
}

// Stage a 64x64 fp32 block (row stride gstride) into split-bf16 smem, row stride 72.
__device__ __forceinline__ void stage_tile(const float* gsrc, int gstride,
                                           ushort* hi, ushort* lo,
                                           int sr, int sq, bool valid)
{
    const float4* src = (const float4*)(gsrc + (size_t)sr * gstride + sq * 16);
    int sbase = sr * 72 + sq * 16;
#pragma unroll
    for (int j = 0; j < 4; j++) {
        float4 v = valid ? src[j] : make_float4(0.f, 0.f, 0.f, 0.f);
        __nv_bfloat162 h0 = __floats2bfloat162_rn(v.x, v.y);
        float2 f0 = __bfloat1622float2(h0);
        __nv_bfloat162 l0 = __floats2bfloat162_rn(v.x - f0.x, v.y - f0.y);
        __nv_bfloat162 h1 = __floats2bfloat162_rn(v.z, v.w);
        float2 f1 = __bfloat1622float2(h1);
        __nv_bfloat162 l1 = __floats2bfloat162_rn(v.z - f1.x, v.w - f1.y);
        *(uint*)(hi + sbase + j * 4)     = *(uint*)&h0;
        *(uint*)(hi + sbase + j * 4 + 2) = *(uint*)&h1;
        *(uint*)(lo + sbase + j * 4)     = *(uint*)&l0;
        *(uint*)(lo + sbase + j * 4 + 2) = *(uint*)&l1;
    }
}

// One 64x64x64 split-bf16 GEMM pass: D += A*B (3 mma passes: hh, lh, hl)
__device__ __forceinline__ void gemm_pass(float d[4][4], uint aoh, uint aol,
                                          uint bbh, uint bbl,
                                          int wn, int lrow, int lcol8)
{
#pragma unroll
    for (int ks = 0; ks < 4; ks++) {
        uint ah[4], al[4];
        ldsm4(ah, aoh + ks * 32);
        ldsm4(al, aol + ks * 32);
#pragma unroll
        for (int ns = 0; ns < 2; ns++) {
            uint boff = (uint)((ks * 16 + lrow) * 144 + (wn * 32 + ns * 16 + lcol8) * 2);
            uint bh[4], bl[4];
            ldsm4t(bh, bbh + boff);
            ldsm4t(bl, bbl + boff);
            mma_bf16(d[ns * 2 + 0], ah, bh[0], bh[1]);
            mma_bf16(d[ns * 2 + 1], ah, bh[2], bh[3]);
            mma_bf16(d[ns * 2 + 0], al, bh[0], bh[1]);
            mma_bf16(d[ns * 2 + 1], al, bh[2], bh[3]);
            mma_bf16(d[ns * 2 + 0], ah, bl[0], bl[1]);
            mma_bf16(d[ns * 2 + 1], ah, bl[2], bl[3]);
        }
    }
}

__global__ __launch_bounds__(256) void k_node(
    const float* __restrict__ X,
    const float* __restrict__ b1, const float* __restrict__ g1,
    const float* __restrict__ be1, const float* __restrict__ b2,
    const float* __restrict__ W1, const float* __restrict__ W2,
    const float* __restrict__ Wm1)
{
    __shared__ __align__(16) char sm0[18432];   // A hi/lo (bf16)  OR  sY fp32 [64][66]
    __shared__ __align__(16) char sm1[18432];   // B hi/lo (bf16)
    __shared__ float sb1[64], sg1[64], sbe1[64], sb2[64];

    ushort* sAh = (ushort*)sm0;
    ushort* sAl = (ushort*)(sm0 + 9216);
    ushort* sBh = (ushort*)sm1;
    ushort* sBl = (ushort*)(sm1 + 9216);
    float*  sY  = (float*)sm0;                  // stride 66

    int tid = threadIdx.x;
    int lane = tid & 31, w = tid >> 5;
    int wm = w & 3, wn = w >> 2;                // warp tile: rows wm*16, cols wn*32
    int n0 = blockIdx.x * TILE;
    int nvalid = min(TILE, Nn - n0);
    if (tid < 64) { sb1[tid] = b1[tid]; sg1[tid] = g1[tid]; sbe1[tid] = be1[tid]; sb2[tid] = b2[tid]; }

    int lrow = lane & 15, lcol8 = (lane >> 4) * 8;
    uint aoh = smem_u32(sAh) + (uint)((wm * 16 + lrow) * 144 + lcol8 * 2);
    uint aol = smem_u32(sAl) + (uint)((wm * 16 + lrow) * 144 + lcol8 * 2);
    uint bbh = smem_u32(sBh);
    uint bbl = smem_u32(sBl);

    int sr = tid >> 2, sq = tid & 3;            // staging: row, 16-col quarter
    int erow = wm * 16 + (lane >> 2);           // epilogue row0 (row1 = +8)
    int ecol = wn * 32 + 2 * (lane & 3);        // epilogue col base; frag f adds f*8
    bool v0r = erow < nvalid, v1r = erow + 8 < nvalid;

    // ---- GEMM1: Y = X @ W1 (K=256, 4 chunks) ----
    float d1[4][4];
#pragma unroll
    for (int f = 0; f < 4; f++) { d1[f][0] = d1[f][1] = d1[f][2] = d1[f][3] = 0.f; }
    for (int kc = 0; kc < 4; kc++) {
        stage_tile(X + (size_t)n0 * Ff + kc * 64, Ff, sAh, sAl, sr, sq, sr < nvalid);
        stage_tile(W1 + kc * 64 * 64, 64, sBh, sBl, sr, sq, true);
        __syncthreads();
        gemm_pass(d1, aoh, aol, bbh, bbl, wn, lrow, lcol8);
        __syncthreads();
    }

    // epilogue 1: Y + b1 -> sY (fp32, stride 66); stage W2 into sB
#pragma unroll
    for (int f = 0; f < 4; f++) {
        int c = ecol + f * 8;
        float b0 = sb1[c], b1v = sb1[c + 1];
        *(float2*)(sY + erow * 66 + c)       = make_float2(d1[f][0] + b0, d1[f][1] + b1v);
        *(float2*)(sY + (erow + 8) * 66 + c) = make_float2(d1[f][2] + b0, d1[f][3] + b1v);
    }
    stage_tile(W2, 64, sBh, sBl, sr, sq, true);
    __syncthreads();

    // LN + relu: 4 threads/row via shfl, then convert into sA (aliases sY)
    {
        float yv[16];
        float s = 0.f, s2 = 0.f;
#pragma unroll
        for (int c = 0; c < 16; c++) {
            float x = sY[sr * 66 + sq * 16 + c];
            yv[c] = x; s += x; s2 += x * x;
        }
        s  += __shfl_xor_sync(0xFFFFFFFFu, s, 1);  s2 += __shfl_xor_sync(0xFFFFFFFFu, s2, 1);
        s  += __shfl_xor_sync(0xFFFFFFFFu, s, 2);  s2 += __shfl_xor_sync(0xFFFFFFFFu, s2, 2);
        float mu = s * (1.f / 64.f);
        float var = s2 * (1.f / 64.f) - mu * mu;
        float rs = rsqrtf(var + 1e-5f);
#pragma unroll
        for (int c = 0; c < 16; c++) {
            int cc = sq * 16 + c;
            yv[c] = fmaxf((yv[c] - mu) * rs * sg1[cc] + sbe1[cc], 0.f);
        }
        __syncthreads();   // all sY reads done before overwriting with bf16
        int sbase = sr * 72 + sq * 16;
#pragma unroll
        for (int j = 0; j < 8; j++) {
            __nv_bfloat162 h2 = __floats2bfloat162_rn(yv[2 * j], yv[2 * j + 1]);
            float2 hf = __bfloat1622float2(h2);
            __nv_bfloat162 l2 = __floats2bfloat162_rn(yv[2 * j] - hf.x, yv[2 * j + 1] - hf.y);
            *(uint*)(sAh + sbase + 2 * j) = *(uint*)&h2;
            *(uint*)(sAl + sbase + 2 * j) = *(uint*)&l2;
        }
    }
    __syncthreads();

    // ---- GEMM2: h = relu(D2 + b2) ----
    float d2[4][4];
#pragma unroll
    for (int f = 0; f < 4; f++) { d2[f][0] = d2[f][1] = d2[f][2] = d2[f][3] = 0.f; }
    gemm_pass(d2, aoh, aol, bbh, bbl, wn, lrow, lcol8);
    __syncthreads();

    // epilogue 2: h -> d_h (fp32 global) + sA (bf16); stage Wm1a
#pragma unroll
    for (int f = 0; f < 4; f++) {
        int c = ecol + f * 8;
        float b0 = sb2[c], b1v = sb2[c + 1];
        float h00 = fmaxf(d2[f][0] + b0, 0.f), h01 = fmaxf(d2[f][1] + b1v, 0.f);
        float h10 = fmaxf(d2[f][2] + b0, 0.f), h11 = fmaxf(d2[f][3] + b1v, 0.f);
        if (v0r) *(float2*)(d_h + (size_t)(n0 + erow)     * 64 + c) = make_float2(h00, h01);
        if (v1r) *(float2*)(d_h + (size_t)(n0 + erow + 8) * 64 + c) = make_float2(h10, h11);
        __nv_bfloat162 h2a = __floats2bfloat162_rn(h00, h01);
        float2 fa = __bfloat1622float2(h2a);
        __nv_bfloat162 l2a = __floats2bfloat162_rn(h00 - fa.x, h01 - fa.y);
        *(uint*)(sAh + erow * 72 + c) = *(uint*)&h2a;
        *(uint*)(sAl + erow * 72 + c) = *(uint*)&l2a;
        __nv_bfloat162 h2b = __floats2bfloat162_rn(h10, h11);
        float2 fb = __bfloat1622float2(h2b);
        __nv_bfloat162 l2b = __floats2bfloat162_rn(h10 - fb.x, h11 - fb.y);
        *(uint*)(sAh + (erow + 8) * 72 + c) = *(uint*)&h2b;
        *(uint*)(sAl + (erow + 8) * 72 + c) = *(uint*)&l2b;
    }
    stage_tile(Wm1, 64, sBh, sBl, sr, sq, true);
    __syncthreads();

    // ---- GEMM3: A = h @ Wm1[0:64], fp16 stores ----
    float d3[4][4];
#pragma unroll
    for (int f = 0; f < 4; f++) { d3[f][0] = d3[f][1] = d3[f][2] = d3[f][3] = 0.f; }
    gemm_pass(d3, aoh, aol, bbh, bbl, wn, lrow, lcol8);
    __syncthreads();
#pragma unroll
    for (int f = 0; f < 4; f++) {
        int c = ecol + f * 8;
        if (v0r) *(__half2*)(d_A + (size_t)(n0 + erow)     * 64 + c) = __floats2half2_rn(d3[f][0], d3[f][1]);
        if (v1r) *(__half2*)(d_A + (size_t)(n0 + erow + 8) * 64 + c) = __floats2half2_rn(d3[f][2], d3[f][3]);
    }
    stage_tile(Wm1 + 64 * 64, 64, sBh, sBl, sr, sq, true);
    __syncthreads();

    // ---- GEMM4: B = h @ Wm1[64:128], fp16 stores ----
    float d4[4][4];
#pragma unroll
    for (int f = 0; f < 4; f++) { d4[f][0] = d4[f][1] = d4[f][2] = d4[f][3] = 0.f; }
    gemm_pass(d4, aoh, aol, bbh, bbl, wn, lrow, lcol8);
#pragma unroll
    for (int f = 0; f < 4; f++) {
        int c = ecol + f * 8;
        if (v0r) *(__half2*)(d_B + (size_t)(n0 + erow)     * 64 + c) = __floats2half2_rn(d4[f][0], d4[f][1]);
        if (v1r) *(__half2*)(d_B + (size_t)(n0 + erow + 8) * 64 + c) = __floats2half2_rn(d4[f][2], d4[f][3]);
    }

    // fused init: zero this tile's d_S rows (fp16: 128B/row) and d_cnt
#pragma unroll
    for (int i = 0; i < 2; i++) {
        int idx = tid + i * 256;          // 0..511
        int r = idx >> 3, q = idx & 7;
        if (r < nvalid)
            ((uint4*)(d_S + (size_t)(n0 + r) * 64))[q] = make_uint4(0u, 0u, 0u, 0u);
    }
    if (tid < TILE && tid < nvalid) d_cnt[n0 + tid] = 0.f;
}

// Edge pass: 2 edges per 16-lane group, fp16 A/B gathers + fp16 vector atomics
__global__ __launch_bounds__(256) void k_edge(
    const float* __restrict__ edges,
    const float* __restrict__ Wm1, const float* __restrict__ bm1)
{
    __shared__ float sC[Rr * 64];
    __shared__ float swl[64], sbm1[64];
    int tid = threadIdx.x;
    for (int i = tid; i < Rr * 64; i += 256) sC[i] = d_C[i];
    if (tid < 64) { swl[tid] = Wm1[192 * 64 + tid]; sbm1[tid] = bm1[tid]; }
    __syncthreads();

    const int half = Ee / 2;
    int g = (blockIdx.x * 256 + tid) >> 4;
    int sub = tid & 15;
    if (g >= half) return;
    int c4 = sub * 4;

    float4 e0 = *(const float4*)(edges + (size_t)g * 4);
    float4 e1 = *(const float4*)(edges + (size_t)(g + half) * 4);
    int s0 = (int)e0.x, d0 = (int)e0.y, r0 = (int)e0.z; float w0 = e0.w;
    int s1 = (int)e1.x, d1 = (int)e1.y, r1 = (int)e1.z; float w1 = e1.w;

    uint2 au0 = *(const uint2*)(d_A + (size_t)s0 * 64 + c4);
    uint2 bu0 = *(const uint2*)(d_B + (size_t)d0 * 64 + c4);
    uint2 au1 = *(const uint2*)(d_A + (size_t)s1 * 64 + c4);
    uint2 bu1 = *(const uint2*)(d_B + (size_t)d1 * 64 + c4);

    float2 a0lo = __half22float2(*(__half2*)&au0.x), a0hi = __half22float2(*(__half2*)&au0.y);
    float2 b0lo = __half22float2(*(__half2*)&bu0.x), b0hi = __half22float2(*(__half2*)&bu0.y);
    float2 a1lo = __half22float2(*(__half2*)&au1.x), a1hi = __half22float2(*(__half2*)&au1.y);
    float2 b1lo = __half22float2(*(__half2*)&bu1.x), b1hi = __half22float2(*(__half2*)&bu1.y);

    float4 c0v = *(const float4*)(sC + r0 * 64 + c4);
    float4 c1v = *(const float4*)(sC + r1 * 64 + c4);
    float4 wl = *(const float4*)(swl + c4);
    float4 bm = *(const float4*)(sbm1 + c4);

    float4 v0, v1;
    v0.x = fmaxf(a0lo.x + b0lo.x + c0v.x + w0 * wl.x + bm.x, 0.f);
    v0.y = fmaxf(a0lo.y + b0lo.y + c0v.y + w0 * wl.y + bm.y, 0.f);
    v0.z = fmaxf(a0hi.x + b0hi.x + c0v.z + w0 * wl.z + bm.z, 0.f);
    v0.w = fmaxf(a0hi.y + b0hi.y + c0v.w + w0 * wl.w + bm.w, 0.f);
    v1.x = fmaxf(a1lo.x + b1lo.x + c1v.x + w1 * wl.x + bm.x, 0.f);
    v1.y = fmaxf(a1lo.y + b1lo.y + c1v.y + w1 * wl.y + bm.y, 0.f);
    v1.z = fmaxf(a1hi.x + b1hi.x + c1v.z + w1 * wl.z + bm.z, 0.f);
    v1.w = fmaxf(a1hi.y + b1hi.y + c1v.w + w1 * wl.w + bm.w, 0.f);

    __half2 p0lo = __floats2half2_rn(v0.x, v0.y), p0hi = __floats2half2_rn(v0.z, v0.w);
    __half2 p1lo = __floats2half2_rn(v1.x, v1.y), p1hi = __floats2half2_rn(v1.z, v1.w);

    __half* p0 = d_S + (size_t)d0 * 64 + c4;
    __half* p1 = d_S + (size_t)d1 * 64 + c4;
    asm volatile("red.global.add.noftz.v2.f16x2 [%0], {%1,%2};"
                 :: "l"(p0), "r"(*(uint*)&p0lo), "r"(*(uint*)&p0hi) : "memory");
    asm volatile("red.global.add.noftz.v2.f16x2 [%0], {%1,%2};"
                 :: "l"(p1), "r"(*(uint*)&p1lo), "r"(*(uint*)&p1hi) : "memory");
    if (sub == 0) { atomicAdd(&d_cnt[d0], 1.f); atomicAdd(&d_cnt[d1], 1.f); }
}

__global__ __launch_bounds__(256) void k_agg(
    const float* __restrict__ Wm2, const float* __restrict__ bm2,
    const float* __restrict__ gn,  const float* __restrict__ bn)
{
    __shared__ __align__(16) float buf[64 * BS];
    __shared__ __align__(16) float sW[64 * 64];
    __shared__ float sbm2[64], sgn[64], sbn[64];
    __shared__ float red_s[4 * 64];
    __shared__ float red_m[4 * 64];

    int tid = threadIdx.x;
    int n0 = blockIdx.x * TILE;
    int nvalid = min(TILE, Nn - n0);
    if (tid < 64) { sbm2[tid] = bm2[tid]; sgn[tid] = gn[tid]; sbn[tid] = bn[tid]; }

    for (int i = 0; i < 4; i++) {
        int f = tid + i * 256;
        int r = f & 63;
        int k4 = (f >> 6) * 4;
        float4 v = make_float4(0.f, 0.f, 0.f, 0.f);
        if (r < nvalid) {
            uint2 hv = *(const uint2*)(d_S + (size_t)(n0 + r) * 64 + k4);
            float2 lo = __half22float2(*(__half2*)&hv.x);
            float2 hi = __half22float2(*(__half2*)&hv.y);
            v = make_float4(lo.x, lo.y, hi.x, hi.y);
        }
        buf[(k4 + 0) * BS + r] = v.x;
        buf[(k4 + 1) * BS + r] = v.y;
        buf[(k4 + 2) * BS + r] = v.z;
        buf[(k4 + 3) * BS + r] = v.w;
    }
    for (int i = 0; i < 4; i++) {
        int f = tid + i * 256;
        *(float4*)(sW + f * 4) = *(const float4*)(Wm2 + f * 4);
    }
    __syncthreads();

    int tx = tid & 31, ty = tid >> 5;
    int c0 = 2 * tx, r0 = 8 * ty;
    ull acc[4][2];
#pragma unroll
    for (int p = 0; p < 4; p++) { acc[p][0] = 0ull; acc[p][1] = 0ull; }
#pragma unroll 4
    for (int k = 0; k < 64; k++) {
        ulonglong2 xa = *(const ulonglong2*)(buf + k * BS + r0);
        ulonglong2 xb = *(const ulonglong2*)(buf + k * BS + r0 + 4);
        float2 w = *(const float2*)(sW + k * 64 + c0);
        ull wd0 = pk2(w.x, w.x), wd1 = pk2(w.y, w.y);
        fma2(acc[0][0], xa.x, wd0); fma2(acc[0][1], xa.x, wd1);
        fma2(acc[1][0], xa.y, wd0); fma2(acc[1][1], xa.y, wd1);
        fma2(acc[2][0], xb.x, wd0); fma2(acc[2][1], xb.x, wd1);
        fma2(acc[3][0], xb.y, wd0); fma2(acc[3][1], xb.y, wd1);
    }
    __syncthreads();

#pragma unroll
    for (int p = 0; p < 4; p++) {
        int rr = r0 + 2 * p;
        float cnt0 = (rr     < nvalid) ? d_cnt[n0 + rr]     : 0.f;
        float cnt1 = (rr + 1 < nvalid) ? d_cnt[n0 + rr + 1] : 0.f;
        float2 h0 = (rr     < nvalid) ? *(const float2*)(d_h + (size_t)(n0 + rr)     * 64 + c0) : make_float2(0.f, 0.f);
        float2 h1 = (rr + 1 < nvalid) ? *(const float2*)(d_h + (size_t)(n0 + rr + 1) * 64 + c0) : make_float2(0.f, 0.f);
        float2 v0 = upk2(acc[p][0]);
        float2 v1 = upk2(acc[p][1]);
        buf[(c0    ) * BS + rr    ] = v0.x + cnt0 * sbm2[c0    ] + h0.x;
        buf[(c0    ) * BS + rr + 1] = v0.y + cnt1 * sbm2[c0    ] + h1.x;
        buf[(c0 + 1) * BS + rr    ] = v1.x + cnt0 * sbm2[c0 + 1] + h0.y;
        buf[(c0 + 1) * BS + rr + 1] = v1.y + cnt1 * sbm2[c0 + 1] + h1.y;
    }
    __syncthreads();

    if (tid < 64 && tid < nvalid) {
        int r = tid;
        float s = 0.f, s2 = 0.f;
        for (int c = 0; c < 64; c++) { float x = buf[c * BS + r]; s += x; s2 += x * x; }
        float mu = s * (1.f / 64.f);
        float var = s2 * (1.f / 64.f) - mu * mu;
        float rs = rsqrtf(var + 1e-5f);
        for (int c = 0; c < 64; c++) {
            float x = buf[c * BS + r];
            buf[c * BS + r] = (x - mu) * rs * sgn[c] + sbn[c];
        }
    }
    __syncthreads();

    {
        int c = tid & 63, q = tid >> 6;
        float s = 0.f, m = -FLT_MAX;
        int rbeg = q * 16;
        int rend = min(rbeg + 16, nvalid);
        for (int r = rbeg; r < rend; r++) {
            float v = buf[c * BS + r];
            s += v;
            m = fmaxf(m, v);
        }
        red_s[q * 64 + c] = s;
        red_m[q * 64 + c] = m;
    }
    __syncthreads();
    if (tid < 64) {
        float s = red_s[tid] + red_s[64 + tid] + red_s[128 + tid] + red_s[192 + tid];
        float m = fmaxf(fmaxf(red_m[tid], red_m[64 + tid]),
                        fmaxf(red_m[128 + tid], red_m[192 + tid]));
        atomicAdd(&d_colsum[tid], s);
        atomicMaxFloat(&d_colmax[tid], m);
    }
}

__global__ void k_final(const float* __restrict__ Wg1, const float* __restrict__ bg1,
                        const float* __restrict__ Wg2, const float* __restrict__ bg2,
                        float* __restrict__ out)
{
    __shared__ float sg[128], st[64];
    int t = threadIdx.x;
    if (t < 64)       sg[t] = d_colsum[t] * (1.0f / (float)Nn);
    else if (t < 128) sg[t] = __int_as_float(d_colmax[t - 64]);
    __syncthreads();
    if (t < 64) {
        float s = bg1[t];
        for (int k = 0; k < 128; k++) s += sg[k] * Wg1[k * 64 + t];
        st[t] = fmaxf(s, 0.f);
    }
    __syncthreads();
    if (t < 64) {
        float s = bg2[t];
        for (int k = 0; k < 64; k++) s += st[k] * Wg2[k * 64 + t];
        out[t] = s;
    }
}

extern "C" void kernel_launch(void* const* d_in, const int* in_sizes, int n_in,
                              void* d_out, int out_size)
{
    const float* X      = (const float*)d_in[0];
    const float* edges  = (const float*)d_in[1];
    const float* W1     = (const float*)d_in[2];
    const float* b1     = (const float*)d_in[3];
    const float* g1     = (const float*)d_in[4];
    const float* be1    = (const float*)d_in[5];
    const float* W2     = (const float*)d_in[6];
    const float* b2     = (const float*)d_in[7];
    const float* rel_emb= (const float*)d_in[8];
    const float* Wm1    = (const float*)d_in[9];
    const float* bm1    = (const float*)d_in[10];
    const float* Wm2    = (const float*)d_in[11];
    const float* bm2    = (const float*)d_in[12];
    const float* gn     = (const float*)d_in[13];
    const float* bn     = (const float*)d_in[14];
    const float* Wg1    = (const float*)d_in[15];
    const float* bg1    = (const float*)d_in[16];
    const float* Wg2    = (const float*)d_in[17];
    const float* bg2    = (const float*)d_in[18];
    float* out = (float*)d_out;

    k_relC<<<1, 512>>>(rel_emb, Wm1);
    int nblocks = (Nn + TILE - 1) / TILE;
    k_node<<<nblocks, 256>>>(X, b1, g1, be1, b2, W1, W2, Wm1);
    int eblocks = ((Ee / 2) * 16 + 255) / 256;
    k_edge<<<eblocks, 256>>>(edges, Wm1, bm1);
    k_agg<<<nblocks, 256>>>(Wm2, bm2, gn, bn);
    k_final<<<1, 128>>>(Wg1, bg1, Wg2, bg2, out);
}

// round 16
// speedup vs baseline: 1.4999x; 1.0916x over previous
#include <cuda_runtime.h>
#include <cuda_bf16.h>
#include <cuda_fp16.h>
#include <math.h>
#include <float.h>

#define Nn 100000
#define Ff 256
#define Hh 64
#define Ee 800000
#define Rr 7
#define TILE 64
#define BS 68

typedef unsigned long long ull;
typedef unsigned int uint;
typedef unsigned short ushort;

__device__ float  d_h[Nn * Hh];
__device__ __half d_A[Nn * Hh];
__device__ __half d_B[Nn * Hh];
__device__ __half d_S[Nn * Hh];
__device__ float d_cnt[Nn];
__device__ float d_C[Rr * Hh];
__device__ float d_colsum[Hh];
__device__ int   d_colmax[Hh];

// pre-split bf16 weight images, smem layout (row stride 72), hi then lo contiguous
// 0-3: W1 chunks, 4: W2, 5: Wm1[0:64], 6: Wm1[64:128]
__device__ __align__(16) ushort d_iW[7][2][64 * 72];

__device__ __forceinline__ ull pk2(float a, float b) {
    ull r; asm("mov.b64 %0, {%1,%2};" : "=l"(r) : "f"(a), "f"(b)); return r;
}
__device__ __forceinline__ float2 upk2(ull v) {
    float2 f; asm("mov.b64 {%0,%1}, %2;" : "=f"(f.x), "=f"(f.y) : "l"(v)); return f;
}
__device__ __forceinline__ void fma2(ull &d, ull a, ull b) {
    asm("fma.rn.f32x2 %0, %1, %2, %0;" : "+l"(d) : "l"(a), "l"(b));
}
__device__ __forceinline__ void atomicMaxFloat(int* addr, float v) {
    if (v >= 0.f) atomicMax(addr, __float_as_int(v));
    else          atomicMin((unsigned int*)addr, __float_as_uint(v));
}
__device__ __forceinline__ uint smem_u32(const void* p) {
    uint a; asm("{ .reg .u64 t; cvta.to.shared.u64 t, %1; cvt.u32.u64 %0, t; }" : "=r"(a) : "l"(p));
    return a;
}
__device__ __forceinline__ void ldsm4(uint* r, uint addr) {
    asm volatile("ldmatrix.sync.aligned.m8n8.x4.shared.b16 {%0,%1,%2,%3}, [%4];"
        : "=r"(r[0]), "=r"(r[1]), "=r"(r[2]), "=r"(r[3]) : "r"(addr));
}
__device__ __forceinline__ void ldsm4t(uint* r, uint addr) {
    asm volatile("ldmatrix.sync.aligned.m8n8.x4.trans.shared.b16 {%0,%1,%2,%3}, [%4];"
        : "=r"(r[0]), "=r"(r[1]), "=r"(r[2]), "=r"(r[3]) : "r"(addr));
}
__device__ __forceinline__ void mma_bf16(float* d, const uint* a, uint b0, uint b1) {
    asm volatile("mma.sync.aligned.m16n8k16.row.col.f32.bf16.bf16.f32 "
        "{%0,%1,%2,%3}, {%4,%5,%6,%7}, {%8,%9}, {%0,%1,%2,%3};"
        : "+f"(d[0]), "+f"(d[1]), "+f"(d[2]), "+f"(d[3])
        : "r"(a[0]), "r"(a[1]), "r"(a[2]), "r"(a[3]), "r"(b0), "r"(b1));
}

// colsum/colmax init folded in here
__global__ void k_relC(const float* __restrict__ rel_emb, const float* __restrict__ Wm1) {
    int t = threadIdx.x;
    if (t < Hh) { d_colsum[t] = 0.f; d_colmax[t] = __float_as_int(-FLT_MAX); }
    if (t >= Rr * Hh) return;
    int r = t / Hh, j = t % Hh;
    float s = 0.f;
    for (int k = 0; k < Hh; k++) s += rel_emb[r * Hh + k] * Wm1[(128 + k) * Hh + j];
    d_C[t] = s;
}

// Build split-bf16 weight images in the exact smem layout (stride 72).
__global__ void k_prep(const float* __restrict__ W1, const float* __restrict__ W2,
                       const float* __restrict__ Wm1)
{
    int idx = blockIdx.x * blockDim.x + threadIdx.x;
    if (idx >= 7 * 4096) return;
    int img = idx >> 12, rem = idx & 4095;
    int k = rem >> 6, n = rem & 63;
    float v;
    if (img < 4)       v = W1[img * 4096 + rem];
    else if (img == 4) v = W2[rem];
    else if (img == 5) v = Wm1[rem];
    else               v = Wm1[4096 + rem];
    __nv_bfloat16 hb = __float2bfloat16_rn(v);
    float hv = __bfloat162float(hb);
    __nv_bfloat16 lb = __float2bfloat16_rn(v - hv);
    d_iW[img][0][k * 72 + n] = *(ushort*)&hb;
    d_iW[img][1][k * 72 + n] = *(ushort*)&lb;
}

// Stage a 64x64 fp32 block (row stride gstride) into split-bf16 smem, row stride 72.
__device__ __forceinline__ void stage_tile(const float* gsrc, int gstride,
                                           ushort* hi, ushort* lo,
                                           int sr, int sq, bool valid)
{
    const float4* src = (const float4*)(gsrc + (size_t)sr * gstride + sq * 16);
    int sbase = sr * 72 + sq * 16;
#pragma unroll
    for (int j = 0; j < 4; j++) {
        float4 v = valid ? src[j] : make_float4(0.f, 0.f, 0.f, 0.f);
        __nv_bfloat162 h0 = __floats2bfloat162_rn(v.x, v.y);
        float2 f0 = __bfloat1622float2(h0);
        __nv_bfloat162 l0 = __floats2bfloat162_rn(v.x - f0.x, v.y - f0.y);
        __nv_bfloat162 h1 = __floats2bfloat162_rn(v.z, v.w);
        float2 f1 = __bfloat1622float2(h1);
        __nv_bfloat162 l1 = __floats2bfloat162_rn(v.z - f1.x, v.w - f1.y);
        *(uint*)(hi + sbase + j * 4)     = *(uint*)&h0;
        *(uint*)(hi + sbase + j * 4 + 2) = *(uint*)&h1;
        *(uint*)(lo + sbase + j * 4)     = *(uint*)&l0;
        *(uint*)(lo + sbase + j * 4 + 2) = *(uint*)&l1;
    }
}

// copy a pre-split weight image (hi+lo, 18432B contiguous) into sm1
#define STAGE_W(IMG) do {                                                     \
    const uint2* _s = (const uint2*)d_iW[IMG];                                \
    uint2* _d = (uint2*)sm1;                                                  \
    _Pragma("unroll")                                                         \
    for (int _i = 0; _i < 9; _i++) _d[tid + _i * 256] = _s[tid + _i * 256];   \
} while (0)

// 3-pass split-bf16 64x64x64 GEMM: D += A*B (hh + lh + hl)
__device__ __forceinline__ void gemm_pass(float d[4][4], uint aoh, uint aol,
                                          uint bbh, uint bbl,
                                          int wn, int lrow, int lcol8)
{
#pragma unroll
    for (int ks = 0; ks < 4; ks++) {
        uint ah[4], al[4];
        ldsm4(ah, aoh + ks * 32);
        ldsm4(al, aol + ks * 32);
#pragma unroll
        for (int ns = 0; ns < 2; ns++) {
            uint boff = (uint)((ks * 16 + lrow) * 144 + (wn * 32 + ns * 16 + lcol8) * 2);
            uint bh[4], bl[4];
            ldsm4t(bh, bbh + boff);
            ldsm4t(bl, bbl + boff);
            mma_bf16(d[ns * 2 + 0], ah, bh[0], bh[1]);
            mma_bf16(d[ns * 2 + 1], ah, bh[2], bh[3]);
            mma_bf16(d[ns * 2 + 0], al, bh[0], bh[1]);
            mma_bf16(d[ns * 2 + 1], al, bh[2], bh[3]);
            mma_bf16(d[ns * 2 + 0], ah, bl[0], bl[1]);
            mma_bf16(d[ns * 2 + 1], ah, bl[2], bl[3]);
        }
    }
}

// 2-pass variant (hh + lh) for GEMMs whose output is fp16-truncated anyway
__device__ __forceinline__ void gemm_pass2(float d[4][4], uint aoh, uint aol,
                                           uint bbh, int wn, int lrow, int lcol8)
{
#pragma unroll
    for (int ks = 0; ks < 4; ks++) {
        uint ah[4], al[4];
        ldsm4(ah, aoh + ks * 32);
        ldsm4(al, aol + ks * 32);
#pragma unroll
        for (int ns = 0; ns < 2; ns++) {
            uint boff = (uint)((ks * 16 + lrow) * 144 + (wn * 32 + ns * 16 + lcol8) * 2);
            uint bh[4];
            ldsm4t(bh, bbh + boff);
            mma_bf16(d[ns * 2 + 0], ah, bh[0], bh[1]);
            mma_bf16(d[ns * 2 + 1], ah, bh[2], bh[3]);
            mma_bf16(d[ns * 2 + 0], al, bh[0], bh[1]);
            mma_bf16(d[ns * 2 + 1], al, bh[2], bh[3]);
        }
    }
}

__global__ __launch_bounds__(256) void k_node(
    const float* __restrict__ X,
    const float* __restrict__ b1, const float* __restrict__ g1,
    const float* __restrict__ be1, const float* __restrict__ b2)
{
    __shared__ __align__(16) char sm0[18432];   // A hi/lo (bf16)  OR  sY fp32 [64][66]
    __shared__ __align__(16) char sm1[18432];   // B hi/lo (bf16)
    __shared__ float sb1[64], sg1[64], sbe1[64], sb2[64];

    ushort* sAh = (ushort*)sm0;
    ushort* sAl = (ushort*)(sm0 + 9216);
    ushort* sBh = (ushort*)sm1;
    ushort* sBl = (ushort*)(sm1 + 9216);
    float*  sY  = (float*)sm0;                  // stride 66

    int tid = threadIdx.x;
    int lane = tid & 31, w = tid >> 5;
    int wm = w & 3, wn = w >> 2;
    int n0 = blockIdx.x * TILE;
    int nvalid = min(TILE, Nn - n0);
    if (tid < 64) { sb1[tid] = b1[tid]; sg1[tid] = g1[tid]; sbe1[tid] = be1[tid]; sb2[tid] = b2[tid]; }

    int lrow = lane & 15, lcol8 = (lane >> 4) * 8;
    uint aoh = smem_u32(sAh) + (uint)((wm * 16 + lrow) * 144 + lcol8 * 2);
    uint aol = smem_u32(sAl) + (uint)((wm * 16 + lrow) * 144 + lcol8 * 2);
    uint bbh = smem_u32(sBh);
    uint bbl = smem_u32(sBl);

    int sr = tid >> 2, sq = tid & 3;
    int erow = wm * 16 + (lane >> 2);
    int ecol = wn * 32 + 2 * (lane & 3);
    bool v0r = erow < nvalid, v1r = erow + 8 < nvalid;

    // ---- GEMM1: Y = X @ W1 (K=256, 4 chunks, 3-pass) ----
    float d1[4][4];
#pragma unroll
    for (int f = 0; f < 4; f++) { d1[f][0] = d1[f][1] = d1[f][2] = d1[f][3] = 0.f; }
    for (int kc = 0; kc < 4; kc++) {
        stage_tile(X + (size_t)n0 * Ff + kc * 64, Ff, sAh, sAl, sr, sq, sr < nvalid);
        STAGE_W(kc);
        __syncthreads();
        gemm_pass(d1, aoh, aol, bbh, bbl, wn, lrow, lcol8);
        __syncthreads();
    }

    // epilogue 1: Y + b1 -> sY; stage W2
#pragma unroll
    for (int f = 0; f < 4; f++) {
        int c = ecol + f * 8;
        float b0 = sb1[c], b1v = sb1[c + 1];
        *(float2*)(sY + erow * 66 + c)       = make_float2(d1[f][0] + b0, d1[f][1] + b1v);
        *(float2*)(sY + (erow + 8) * 66 + c) = make_float2(d1[f][2] + b0, d1[f][3] + b1v);
    }
    STAGE_W(4);
    __syncthreads();

    // LN + relu: 4 threads/row via shfl, then convert into sA (aliases sY)
    {
        float yv[16];
        float s = 0.f, s2 = 0.f;
#pragma unroll
        for (int c = 0; c < 16; c++) {
            float x = sY[sr * 66 + sq * 16 + c];
            yv[c] = x; s += x; s2 += x * x;
        }
        s  += __shfl_xor_sync(0xFFFFFFFFu, s, 1);  s2 += __shfl_xor_sync(0xFFFFFFFFu, s2, 1);
        s  += __shfl_xor_sync(0xFFFFFFFFu, s, 2);  s2 += __shfl_xor_sync(0xFFFFFFFFu, s2, 2);
        float mu = s * (1.f / 64.f);
        float var = s2 * (1.f / 64.f) - mu * mu;
        float rs = rsqrtf(var + 1e-5f);
#pragma unroll
        for (int c = 0; c < 16; c++) {
            int cc = sq * 16 + c;
            yv[c] = fmaxf((yv[c] - mu) * rs * sg1[cc] + sbe1[cc], 0.f);
        }
        __syncthreads();
        int sbase = sr * 72 + sq * 16;
#pragma unroll
        for (int j = 0; j < 8; j++) {
            __nv_bfloat162 h2 = __floats2bfloat162_rn(yv[2 * j], yv[2 * j + 1]);
            float2 hf = __bfloat1622float2(h2);
            __nv_bfloat162 l2 = __floats2bfloat162_rn(yv[2 * j] - hf.x, yv[2 * j + 1] - hf.y);
            *(uint*)(sAh + sbase + 2 * j) = *(uint*)&h2;
            *(uint*)(sAl + sbase + 2 * j) = *(uint*)&l2;
        }
    }
    __syncthreads();

    // ---- GEMM2: h = relu(D2 + b2), 3-pass ----
    float d2[4][4];
#pragma unroll
    for (int f = 0; f < 4; f++) { d2[f][0] = d2[f][1] = d2[f][2] = d2[f][3] = 0.f; }
    gemm_pass(d2, aoh, aol, bbh, bbl, wn, lrow, lcol8);
    __syncthreads();

    // epilogue 2: h -> d_h (fp32) + sA (bf16); stage Wm1a
#pragma unroll
    for (int f = 0; f < 4; f++) {
        int c = ecol + f * 8;
        float b0 = sb2[c], b1v = sb2[c + 1];
        float h00 = fmaxf(d2[f][0] + b0, 0.f), h01 = fmaxf(d2[f][1] + b1v, 0.f);
        float h10 = fmaxf(d2[f][2] + b0, 0.f), h11 = fmaxf(d2[f][3] + b1v, 0.f);
        if (v0r) *(float2*)(d_h + (size_t)(n0 + erow)     * 64 + c) = make_float2(h00, h01);
        if (v1r) *(float2*)(d_h + (size_t)(n0 + erow + 8) * 64 + c) = make_float2(h10, h11);
        __nv_bfloat162 h2a = __floats2bfloat162_rn(h00, h01);
        float2 fa = __bfloat1622float2(h2a);
        __nv_bfloat162 l2a = __floats2bfloat162_rn(h00 - fa.x, h01 - fa.y);
        *(uint*)(sAh + erow * 72 + c) = *(uint*)&h2a;
        *(uint*)(sAl + erow * 72 + c) = *(uint*)&l2a;
        __nv_bfloat162 h2b = __floats2bfloat162_rn(h10, h11);
        float2 fb = __bfloat1622float2(h2b);
        __nv_bfloat162 l2b = __floats2bfloat162_rn(h10 - fb.x, h11 - fb.y);
        *(uint*)(sAh + (erow + 8) * 72 + c) = *(uint*)&h2b;
        *(uint*)(sAl + (erow + 8) * 72 + c) = *(uint*)&l2b;
    }
    STAGE_W(5);
    __syncthreads();

    // ---- GEMM3: A = h @ Wm1[0:64], 2-pass, fp16 stores ----
    float d3[4][4];
#pragma unroll
    for (int f = 0; f < 4; f++) { d3[f][0] = d3[f][1] = d3[f][2] = d3[f][3] = 0.f; }
    gemm_pass2(d3, aoh, aol, bbh, wn, lrow, lcol8);
    __syncthreads();
#pragma unroll
    for (int f = 0; f < 4; f++) {
        int c = ecol + f * 8;
        if (v0r) *(__half2*)(d_A + (size_t)(n0 + erow)     * 64 + c) = __floats2half2_rn(d3[f][0], d3[f][1]);
        if (v1r) *(__half2*)(d_A + (size_t)(n0 + erow + 8) * 64 + c) = __floats2half2_rn(d3[f][2], d3[f][3]);
    }
    STAGE_W(6);
    __syncthreads();

    // ---- GEMM4: B = h @ Wm1[64:128], 2-pass, fp16 stores ----
    float d4[4][4];
#pragma unroll
    for (int f = 0; f < 4; f++) { d4[f][0] = d4[f][1] = d4[f][2] = d4[f][3] = 0.f; }
    gemm_pass2(d4, aoh, aol, bbh, wn, lrow, lcol8);
#pragma unroll
    for (int f = 0; f < 4; f++) {
        int c = ecol + f * 8;
        if (v0r) *(__half2*)(d_B + (size_t)(n0 + erow)     * 64 + c) = __floats2half2_rn(d4[f][0], d4[f][1]);
        if (v1r) *(__half2*)(d_B + (size_t)(n0 + erow + 8) * 64 + c) = __floats2half2_rn(d4[f][2], d4[f][3]);
    }

    // fused init: zero this tile's d_S rows (fp16: 128B/row) and d_cnt
#pragma unroll
    for (int i = 0; i < 2; i++) {
        int idx = tid + i * 256;
        int r = idx >> 3, q = idx & 7;
        if (r < nvalid)
            ((uint4*)(d_S + (size_t)(n0 + r) * 64))[q] = make_uint4(0u, 0u, 0u, 0u);
    }
    if (tid < TILE && tid < nvalid) d_cnt[n0 + tid] = 0.f;
}

// Edge pass: 2 edges per 16-lane group, fp16 A/B gathers + fp16 vector atomics
__global__ __launch_bounds__(256) void k_edge(
    const float* __restrict__ edges,
    const float* __restrict__ Wm1, const float* __restrict__ bm1)
{
    __shared__ float sC[Rr * 64];
    __shared__ float swl[64], sbm1[64];
    int tid = threadIdx.x;
    for (int i = tid; i < Rr * 64; i += 256) sC[i] = d_C[i];
    if (tid < 64) { swl[tid] = Wm1[192 * 64 + tid]; sbm1[tid] = bm1[tid]; }
    __syncthreads();

    const int half = Ee / 2;
    int g = (blockIdx.x * 256 + tid) >> 4;
    int sub = tid & 15;
    if (g >= half) return;
    int c4 = sub * 4;

    float4 e0 = *(const float4*)(edges + (size_t)g * 4);
    float4 e1 = *(const float4*)(edges + (size_t)(g + half) * 4);
    int s0 = (int)e0.x, d0 = (int)e0.y, r0 = (int)e0.z; float w0 = e0.w;
    int s1 = (int)e1.x, d1 = (int)e1.y, r1 = (int)e1.z; float w1 = e1.w;

    uint2 au0 = *(const uint2*)(d_A + (size_t)s0 * 64 + c4);
    uint2 bu0 = *(const uint2*)(d_B + (size_t)d0 * 64 + c4);
    uint2 au1 = *(const uint2*)(d_A + (size_t)s1 * 64 + c4);
    uint2 bu1 = *(const uint2*)(d_B + (size_t)d1 * 64 + c4);

    float2 a0lo = __half22float2(*(__half2*)&au0.x), a0hi = __half22float2(*(__half2*)&au0.y);
    float2 b0lo = __half22float2(*(__half2*)&bu0.x), b0hi = __half22float2(*(__half2*)&bu0.y);
    float2 a1lo = __half22float2(*(__half2*)&au1.x), a1hi = __half22float2(*(__half2*)&au1.y);
    float2 b1lo = __half22float2(*(__half2*)&bu1.x), b1hi = __half22float2(*(__half2*)&bu1.y);

    float4 c0v = *(const float4*)(sC + r0 * 64 + c4);
    float4 c1v = *(const float4*)(sC + r1 * 64 + c4);
    float4 wl = *(const float4*)(swl + c4);
    float4 bm = *(const float4*)(sbm1 + c4);

    float4 v0, v1;
    v0.x = fmaxf(a0lo.x + b0lo.x + c0v.x + w0 * wl.x + bm.x, 0.f);
    v0.y = fmaxf(a0lo.y + b0lo.y + c0v.y + w0 * wl.y + bm.y, 0.f);
    v0.z = fmaxf(a0hi.x + b0hi.x + c0v.z + w0 * wl.z + bm.z, 0.f);
    v0.w = fmaxf(a0hi.y + b0hi.y + c0v.w + w0 * wl.w + bm.w, 0.f);
    v1.x = fmaxf(a1lo.x + b1lo.x + c1v.x + w1 * wl.x + bm.x, 0.f);
    v1.y = fmaxf(a1lo.y + b1lo.y + c1v.y + w1 * wl.y + bm.y, 0.f);
    v1.z = fmaxf(a1hi.x + b1hi.x + c1v.z + w1 * wl.z + bm.z, 0.f);
    v1.w = fmaxf(a1hi.y + b1hi.y + c1v.w + w1 * wl.w + bm.w, 0.f);

    __half2 p0lo = __floats2half2_rn(v0.x, v0.y), p0hi = __floats2half2_rn(v0.z, v0.w);
    __half2 p1lo = __floats2half2_rn(v1.x, v1.y), p1hi = __floats2half2_rn(v1.z, v1.w);

    __half* p0 = d_S + (size_t)d0 * 64 + c4;
    __half* p1 = d_S + (size_t)d1 * 64 + c4;
    asm volatile("red.global.add.noftz.v2.f16x2 [%0], {%1,%2};"
                 :: "l"(p0), "r"(*(uint*)&p0lo), "r"(*(uint*)&p0hi) : "memory");
    asm volatile("red.global.add.noftz.v2.f16x2 [%0], {%1,%2};"
                 :: "l"(p1), "r"(*(uint*)&p1lo), "r"(*(uint*)&p1hi) : "memory");
    if (sub == 0) { atomicAdd(&d_cnt[d0], 1.f); atomicAdd(&d_cnt[d1], 1.f); }
}

__global__ __launch_bounds__(256) void k_agg(
    const float* __restrict__ Wm2, const float* __restrict__ bm2,
    const float* __restrict__ gn,  const float* __restrict__ bn)
{
    __shared__ __align__(16) float buf[64 * BS];
    __shared__ __align__(16) float sW[64 * 64];
    __shared__ float sbm2[64], sgn[64], sbn[64];
    __shared__ float red_s[4 * 64];
    __shared__ float red_m[4 * 64];

    int tid = threadIdx.x;
    int n0 = blockIdx.x * TILE;
    int nvalid = min(TILE, Nn - n0);
    if (tid < 64) { sbm2[tid] = bm2[tid]; sgn[tid] = gn[tid]; sbn[tid] = bn[tid]; }

    for (int i = 0; i < 4; i++) {
        int f = tid + i * 256;
        int r = f & 63;
        int k4 = (f >> 6) * 4;
        float4 v = make_float4(0.f, 0.f, 0.f, 0.f);
        if (r < nvalid) {
            uint2 hv = *(const uint2*)(d_S + (size_t)(n0 + r) * 64 + k4);
            float2 lo = __half22float2(*(__half2*)&hv.x);
            float2 hi = __half22float2(*(__half2*)&hv.y);
            v = make_float4(lo.x, lo.y, hi.x, hi.y);
        }
        buf[(k4 + 0) * BS + r] = v.x;
        buf[(k4 + 1) * BS + r] = v.y;
        buf[(k4 + 2) * BS + r] = v.z;
        buf[(k4 + 3) * BS + r] = v.w;
    }
    for (int i = 0; i < 4; i++) {
        int f = tid + i * 256;
        *(float4*)(sW + f * 4) = *(const float4*)(Wm2 + f * 4);
    }
    __syncthreads();

    int tx = tid & 31, ty = tid >> 5;
    int c0 = 2 * tx, r0 = 8 * ty;
    ull acc[4][2];
#pragma unroll
    for (int p = 0; p < 4; p++) { acc[p][0] = 0ull; acc[p][1] = 0ull; }
#pragma unroll 4
    for (int k = 0; k < 64; k++) {
        ulonglong2 xa = *(const ulonglong2*)(buf + k * BS + r0);
        ulonglong2 xb = *(const ulonglong2*)(buf + k * BS + r0 + 4);
        float2 w = *(const float2*)(sW + k * 64 + c0);
        ull wd0 = pk2(w.x, w.x), wd1 = pk2(w.y, w.y);
        fma2(acc[0][0], xa.x, wd0); fma2(acc[0][1], xa.x, wd1);
        fma2(acc[1][0], xa.y, wd0); fma2(acc[1][1], xa.y, wd1);
        fma2(acc[2][0], xb.x, wd0); fma2(acc[2][1], xb.x, wd1);
        fma2(acc[3][0], xb.y, wd0); fma2(acc[3][1], xb.y, wd1);
    }
    __syncthreads();

#pragma unroll
    for (int p = 0; p < 4; p++) {
        int rr = r0 + 2 * p;
        float cnt0 = (rr     < nvalid) ? d_cnt[n0 + rr]     : 0.f;
        float cnt1 = (rr + 1 < nvalid) ? d_cnt[n0 + rr + 1] : 0.f;
        float2 h0 = (rr     < nvalid) ? *(const float2*)(d_h + (size_t)(n0 + rr)     * 64 + c0) : make_float2(0.f, 0.f);
        float2 h1 = (rr + 1 < nvalid) ? *(const float2*)(d_h + (size_t)(n0 + rr + 1) * 64 + c0) : make_float2(0.f, 0.f);
        float2 v0 = upk2(acc[p][0]);
        float2 v1 = upk2(acc[p][1]);
        buf[(c0    ) * BS + rr    ] = v0.x + cnt0 * sbm2[c0    ] + h0.x;
        buf[(c0    ) * BS + rr + 1] = v0.y + cnt1 * sbm2[c0    ] + h1.x;
        buf[(c0 + 1) * BS + rr    ] = v1.x + cnt0 * sbm2[c0 + 1] + h0.y;
        buf[(c0 + 1) * BS + rr + 1] = v1.y + cnt1 * sbm2[c0 + 1] + h1.y;
    }
    __syncthreads();

    if (tid < 64 && tid < nvalid) {
        int r = tid;
        float s = 0.f, s2 = 0.f;
        for (int c = 0; c < 64; c++) { float x = buf[c * BS + r]; s += x; s2 += x * x; }
        float mu = s * (1.f / 64.f);
        float var = s2 * (1.f / 64.f) - mu * mu;
        float rs = rsqrtf(var + 1e-5f);
        for (int c = 0; c < 64; c++) {
            float x = buf[c * BS + r];
            buf[c * BS + r] = (x - mu) * rs * sgn[c] + sbn[c];
        }
    }
    __syncthreads();

    {
        int c = tid & 63, q = tid >> 6;
        float s = 0.f, m = -FLT_MAX;
        int rbeg = q * 16;
        int rend = min(rbeg + 16, nvalid);
        for (int r = rbeg; r < rend; r++) {
            float v = buf[c * BS + r];
            s += v;
            m = fmaxf(m, v);
        }
        red_s[q * 64 + c] = s;
        red_m[q * 64 + c] = m;
    }
    __syncthreads();
    if (tid < 64) {
        float s = red_s[tid] + red_s[64 + tid] + red_s[128 + tid] + red_s[192 + tid];
        float m = fmaxf(fmaxf(red_m[tid], red_m[64 + tid]),
                        fmaxf(red_m[128 + tid], red_m[192 + tid]));
        atomicAdd(&d_colsum[tid], s);
        atomicMaxFloat(&d_colmax[tid], m);
    }
}

__global__ void k_final(const float* __restrict__ Wg1, const float* __restrict__ bg1,
                        const float* __restrict__ Wg2, const float* __restrict__ bg2,
                        float* __restrict__ out)
{
    __shared__ float sg[128], st[64];
    int t = threadIdx.x;
    if (t < 64)       sg[t] = d_colsum[t] * (1.0f / (float)Nn);
    else if (t < 128) sg[t] = __int_as_float(d_colmax[t - 64]);
    __syncthreads();
    if (t < 64) {
        float s = bg1[t];
        for (int k = 0; k < 128; k++) s += sg[k] * Wg1[k * 64 + t];
        st[t] = fmaxf(s, 0.f);
    }
    __syncthreads();
    if (t < 64) {
        float s = bg2[t];
        for (int k = 0; k < 64; k++) s += st[k] * Wg2[k * 64 + t];
        out[t] = s;
    }
}

extern "C" void kernel_launch(void* const* d_in, const int* in_sizes, int n_in,
                              void* d_out, int out_size)
{
    const float* X      = (const float*)d_in[0];
    const float* edges  = (const float*)d_in[1];
    const float* W1     = (const float*)d_in[2];
    const float* b1     = (const float*)d_in[3];
    const float* g1     = (const float*)d_in[4];
    const float* be1    = (const float*)d_in[5];
    const float* W2     = (const float*)d_in[6];
    const float* b2     = (const float*)d_in[7];
    const float* rel_emb= (const float*)d_in[8];
    const float* Wm1    = (const float*)d_in[9];
    const float* bm1    = (const float*)d_in[10];
    const float* Wm2    = (const float*)d_in[11];
    const float* bm2    = (const float*)d_in[12];
    const float* gn     = (const float*)d_in[13];
    const float* bn     = (const float*)d_in[14];
    const float* Wg1    = (const float*)d_in[15];
    const float* bg1    = (const float*)d_in[16];
    const float* Wg2    = (const float*)d_in[17];
    const float* bg2    = (const float*)d_in[18];
    float* out = (float*)d_out;

    k_relC<<<1, 512>>>(rel_emb, Wm1);
    k_prep<<<28, 1024>>>(W1, W2, Wm1);
    int nblocks = (Nn + TILE - 1) / TILE;
    k_node<<<nblocks, 256>>>(X, b1, g1, be1, b2);
    int eblocks = ((Ee / 2) * 16 + 255) / 256;
    k_edge<<<eblocks, 256>>>(edges, Wm1, bm1);
    k_agg<<<nblocks, 256>>>(Wm2, bm2, gn, bn);
    k_final<<<1, 128>>>(Wg1, bg1, Wg2, bg2, out);
}